// round 9
// baseline (speedup 1.0000x reference)
#include <cuda_runtime.h>
#include <cuda_bf16.h>
#include <math.h>
#include <stdint.h>

// Problem constants (match reference)
#define NN      50000
#define EE      600000
#define D_IN    128
#define D_H     128
#define D_OUT   64
#define NLAYERS 3
#define NG      64
#define SLOPE   0.2f

// ---------------------------------------------------------------------------
// Device scratch
// ---------------------------------------------------------------------------
__device__ __align__(16) float g_h [NN * D_H];     // fp32 features (residual/pool)
__device__ __align__(16) float g_hp[NN * D_H];     // GEMM output (aggr gathers fp32)
__device__ __align__(16) uint32_t g_ah[NN * 64];   // packed bf16x2 k-pairs of h (hi)
__device__ __align__(16) uint32_t g_al[NN * 64];   // packed bf16x2 k-pairs of h (lo)
__device__ __align__(16) uint32_t g_wh[4 * 64 * 128];  // packed weights (hi), mat-major
__device__ __align__(16) uint32_t g_wl[4 * 64 * 128];  // packed weights (lo)
__device__ float g_es[NN];
__device__ float g_ed[NN];
__device__ float g_ee[EE];                         // cached per-edge leaky scores
__device__ int   g_deg[NN];
__device__ int   g_start[NN];
__device__ int   g_cur[NN];
__device__ int   g_total;
__device__ int   g_csrc[EE];                       // compact CSR-by-dst source ids
__device__ int   g_is64;

__device__ __forceinline__ float leaky(float x) {
    return x >= 0.f ? x : SLOPE * x;
}

__device__ __forceinline__ int load_idx(const void* p, long long i) {
    return g_is64 ? (int)((const long long*)p)[i] : ((const int*)p)[i];
}

// pack two floats as bf16x2: low half = a (even k), high half = b (odd k)
__device__ __forceinline__ uint32_t pack_bf16(float a, float b) {
    uint32_t r;
    asm("cvt.rn.bf16x2.f32 %0, %1, %2;" : "=r"(r) : "f"(b), "f"(a));
    return r;
}

__device__ __forceinline__ float bf16_hi_val(float x) {
    __nv_bfloat16 h = __float2bfloat16_rn(x);
    return __bfloat162float(h);
}

__device__ __forceinline__ void mma_bf16(float c[4], const uint32_t a[4],
                                         uint32_t b0, uint32_t b1) {
    asm volatile(
        "mma.sync.aligned.m16n8k16.row.col.f32.bf16.bf16.f32 "
        "{%0,%1,%2,%3}, {%4,%5,%6,%7}, {%8,%9}, {%0,%1,%2,%3};\n"
        : "+f"(c[0]), "+f"(c[1]), "+f"(c[2]), "+f"(c[3])
        : "r"(a[0]), "r"(a[1]), "r"(a[2]), "r"(a[3]), "r"(b0), "r"(b1));
}

// ---------------------------------------------------------------------------
// init: zero degrees; parallel index-dtype probe (warp ballot)
// ---------------------------------------------------------------------------
__global__ void k_init(const int* __restrict__ eiw) {
    int i = blockIdx.x * blockDim.x + threadIdx.x;
    if (i < NN) g_deg[i] = 0;
    if (blockIdx.x == 0 && threadIdx.x < 32) {
        int lane = threadIdx.x;
        int nz = (eiw[2 * lane + 1] != 0) | (eiw[2 * (lane + 32) + 1] != 0);
        unsigned bal = __ballot_sync(0xffffffffu, nz);
        if (lane == 0) { g_is64 = (bal == 0u); g_total = 0; }
    }
}

// ---------------------------------------------------------------------------
// Weight pre-pack: 4 matrices (W1, Wg[0..2]) -> bf16 hi/lo, k-pairs packed
// ---------------------------------------------------------------------------
__global__ void k_wpack(const float* __restrict__ W1,
                        const float* __restrict__ Wg) {
    int idx = blockIdx.x * blockDim.x + threadIdx.x;
    if (idx >= 4 * 64 * 128) return;
    int mat = idx >> 13;
    int kp  = (idx >> 7) & 63;
    int n   = idx & 127;
    const float* W = (mat == 0) ? W1 : Wg + (size_t)(mat - 1) * 128 * 128;
    float a = W[(2 * kp) * 128 + n];
    float b = W[(2 * kp + 1) * 128 + n];
    float ha = bf16_hi_val(a), hb = bf16_hi_val(b);
    g_wh[idx] = pack_bf16(a, b);
    g_wl[idx] = pack_bf16(a - ha, b - hb);
}

// ---------------------------------------------------------------------------
// Compact CSR build: hist -> alloc (warp-aggregated cursor) -> scatter
// ---------------------------------------------------------------------------
__global__ void k_hist(const void* __restrict__ ei) {
    int e = blockIdx.x * blockDim.x + threadIdx.x;
    if (e < EE) {
        int d = load_idx(ei, (long long)EE + e);
        if ((unsigned)d < NN) atomicAdd(&g_deg[d], 1);
    }
}

__global__ void k_alloc() {
    int i = blockIdx.x * blockDim.x + threadIdx.x;
    if (i < NN) {
        int dg = g_deg[i];
        int st = atomicAdd(&g_total, dg);
        g_start[i] = st;
        g_cur[i]   = st;
    }
}

__global__ void k_scatter(const void* __restrict__ ei) {
    int e = blockIdx.x * blockDim.x + threadIdx.x;
    if (e < EE) {
        int s = load_idx(ei, e);
        int d = load_idx(ei, (long long)EE + e);
        if ((unsigned)d < NN && (unsigned)s < NN) {
            int pos = atomicAdd(&g_cur[d], 1);
            g_csrc[pos] = s;
        }
    }
}

// ---------------------------------------------------------------------------
// 3xBF16 tensor-core GEMM: C[M,128] = A[M,128] @ B[128,128] (+bias)
// Block 128x128, 256 threads (8 warps, 2x4), warp tile 64x32, BK=16.
// CVT_A: A is fp32 (split in-kernel); else A read pre-packed from g_ah/g_al.
// B always pre-packed from g_wh/g_wl (+ mat*8192).
// PACK_OUT: epilogue also writes packed bf16 hi/lo of C into g_ah/g_al.
// FUSE_ESED: epilogue computes es/ed row-dots with asrc/adst.
// ---------------------------------------------------------------------------
#define PAD 136

template <bool CVT_A, bool FUSE_ESED, bool PACK_OUT>
__device__ __forceinline__ void mma_gemm_body(const float* __restrict__ A,
                                              int mat,
                                              const float* __restrict__ bias,
                                              const float* __restrict__ asrc,
                                              const float* __restrict__ adst,
                                              float* __restrict__ C, int M) {
    __shared__ uint32_t Ah[8][PAD], Al[8][PAD];   // [k-pair][m]
    __shared__ uint32_t Bh[8][PAD], Bl[8][PAD];   // [k-pair][n]
    __shared__ float es_s[128], ed_s[128];

    const uint32_t* __restrict__ Wh = g_wh + (size_t)mat * 8192;
    const uint32_t* __restrict__ Wl = g_wl + (size_t)mat * 8192;

    const int tid  = threadIdx.x;
    const int warp = tid >> 5, lane = tid & 31;
    const int wm = warp >> 2, wn = warp & 3;
    const int gid = lane >> 2, tig = lane & 3;
    const int brow = blockIdx.x * 128;

    if (FUSE_ESED && tid < 128) { es_s[tid] = 0.f; ed_s[tid] = 0.f; }

    const int a_r  = tid & 63;
    const int a_kp = (tid >> 6) * 2;      // k-pair base within chunk (0 or 2)
    const int b_bp = tid >> 5;            // 0..7
    const int b_n  = (tid & 31) * 4;

    float acc[4][4][4];
    #pragma unroll
    for (int mt = 0; mt < 4; mt++)
        #pragma unroll
        for (int nt = 0; nt < 4; nt++)
            #pragma unroll
            for (int c = 0; c < 4; c++) acc[mt][nt][c] = 0.f;

    for (int kc = 0; kc < 128; kc += 16) {
        const int kp0 = kc / 2;           // global k-pair base of this chunk
        // ---- stage A
        #pragma unroll
        for (int p = 0; p < 2; p++) {
            int r = a_r + 64 * p;
            int grow = brow + r;
            if (CVT_A) {
                float4 v = (grow < M) ? *(const float4*)&A[(size_t)grow * 128 + kc + a_kp * 2]
                                      : make_float4(0.f, 0.f, 0.f, 0.f);
                float h0 = bf16_hi_val(v.x), h1 = bf16_hi_val(v.y);
                float h2 = bf16_hi_val(v.z), h3 = bf16_hi_val(v.w);
                Ah[a_kp][r]     = pack_bf16(v.x, v.y);
                Ah[a_kp + 1][r] = pack_bf16(v.z, v.w);
                Al[a_kp][r]     = pack_bf16(v.x - h0, v.y - h1);
                Al[a_kp + 1][r] = pack_bf16(v.z - h2, v.w - h3);
            } else {
                uint2 vh = (grow < M) ? *(const uint2*)&g_ah[(size_t)grow * 64 + kp0 + a_kp]
                                      : make_uint2(0u, 0u);
                uint2 vl = (grow < M) ? *(const uint2*)&g_al[(size_t)grow * 64 + kp0 + a_kp]
                                      : make_uint2(0u, 0u);
                Ah[a_kp][r]     = vh.x;
                Ah[a_kp + 1][r] = vh.y;
                Al[a_kp][r]     = vl.x;
                Al[a_kp + 1][r] = vl.y;
            }
        }
        // ---- stage B (pre-packed)
        {
            *(uint4*)&Bh[b_bp][b_n] = *(const uint4*)&Wh[(size_t)(kp0 + b_bp) * 128 + b_n];
            *(uint4*)&Bl[b_bp][b_n] = *(const uint4*)&Wl[(size_t)(kp0 + b_bp) * 128 + b_n];
        }
        __syncthreads();

        {
            uint32_t ah[4][4], al[4][4];
            #pragma unroll
            for (int mt = 0; mt < 4; mt++) {
                int m0 = wm * 64 + mt * 16 + gid;
                ah[mt][0] = Ah[tig][m0];     ah[mt][1] = Ah[tig][m0 + 8];
                ah[mt][2] = Ah[tig + 4][m0]; ah[mt][3] = Ah[tig + 4][m0 + 8];
                al[mt][0] = Al[tig][m0];     al[mt][1] = Al[tig][m0 + 8];
                al[mt][2] = Al[tig + 4][m0]; al[mt][3] = Al[tig + 4][m0 + 8];
            }
            #pragma unroll
            for (int nt = 0; nt < 4; nt++) {
                int n0 = wn * 32 + nt * 8 + gid;
                uint32_t bh0 = Bh[tig][n0], bh1 = Bh[tig + 4][n0];
                uint32_t bl0 = Bl[tig][n0], bl1 = Bl[tig + 4][n0];
                #pragma unroll
                for (int mt = 0; mt < 4; mt++) {
                    mma_bf16(acc[mt][nt], ah[mt], bh0, bh1);
                    mma_bf16(acc[mt][nt], ah[mt], bl0, bl1);
                    mma_bf16(acc[mt][nt], al[mt], bh0, bh1);
                }
            }
        }
        __syncthreads();
    }

    float as_v[4][2], ad_v[4][2];
    if (FUSE_ESED) {
        #pragma unroll
        for (int nt = 0; nt < 4; nt++) {
            int c0 = wn * 32 + nt * 8 + 2 * tig;
            as_v[nt][0] = asrc[c0]; as_v[nt][1] = asrc[c0 + 1];
            ad_v[nt][0] = adst[c0]; ad_v[nt][1] = adst[c0 + 1];
        }
    }

    #pragma unroll
    for (int mt = 0; mt < 4; mt++) {
        int r0 = brow + wm * 64 + mt * 16 + gid;
        float pe0 = 0.f, pe1 = 0.f, pd0 = 0.f, pd1 = 0.f;
        #pragma unroll
        for (int nt = 0; nt < 4; nt++) {
            int c0 = wn * 32 + nt * 8 + 2 * tig;
            float b0v = bias ? bias[c0]     : 0.f;
            float b1v = bias ? bias[c0 + 1] : 0.f;
            float v00 = acc[mt][nt][0] + b0v, v01 = acc[mt][nt][1] + b1v;
            float v10 = acc[mt][nt][2] + b0v, v11 = acc[mt][nt][3] + b1v;
            if (r0 < M)     *(float2*)&C[(size_t)r0 * 128 + c0]       = make_float2(v00, v01);
            if (r0 + 8 < M) *(float2*)&C[(size_t)(r0 + 8) * 128 + c0] = make_float2(v10, v11);
            if (PACK_OUT) {
                int w0 = c0 >> 1;
                if (r0 < M) {
                    float h0 = bf16_hi_val(v00), h1 = bf16_hi_val(v01);
                    g_ah[(size_t)r0 * 64 + w0] = pack_bf16(v00, v01);
                    g_al[(size_t)r0 * 64 + w0] = pack_bf16(v00 - h0, v01 - h1);
                }
                if (r0 + 8 < M) {
                    float h0 = bf16_hi_val(v10), h1 = bf16_hi_val(v11);
                    g_ah[(size_t)(r0 + 8) * 64 + w0] = pack_bf16(v10, v11);
                    g_al[(size_t)(r0 + 8) * 64 + w0] = pack_bf16(v10 - h0, v11 - h1);
                }
            }
            if (FUSE_ESED) {
                pe0 += v00 * as_v[nt][0] + v01 * as_v[nt][1];
                pe1 += v10 * as_v[nt][0] + v11 * as_v[nt][1];
                pd0 += v00 * ad_v[nt][0] + v01 * ad_v[nt][1];
                pd1 += v10 * ad_v[nt][0] + v11 * ad_v[nt][1];
            }
        }
        if (FUSE_ESED) {
            #pragma unroll
            for (int o = 1; o <= 2; o <<= 1) {
                pe0 += __shfl_xor_sync(0xffffffffu, pe0, o);
                pe1 += __shfl_xor_sync(0xffffffffu, pe1, o);
                pd0 += __shfl_xor_sync(0xffffffffu, pd0, o);
                pd1 += __shfl_xor_sync(0xffffffffu, pd1, o);
            }
            if (tig == 0) {
                int lr = wm * 64 + mt * 16 + gid;
                atomicAdd(&es_s[lr], pe0);     atomicAdd(&es_s[lr + 8], pe1);
                atomicAdd(&ed_s[lr], pd0);     atomicAdd(&ed_s[lr + 8], pd1);
            }
        }
    }

    if (FUSE_ESED) {
        __syncthreads();
        if (tid < 128 && brow + tid < M) {
            g_es[brow + tid] = es_s[tid];
            g_ed[brow + tid] = ed_s[tid];
        }
    }
}

// mlp1: g_h = x @ W1 + b1, also emits packed bf16 h
__global__ void __launch_bounds__(256) k_mma_x(const float* __restrict__ A,
                                               const float* __restrict__ bias) {
    mma_gemm_body<true, false, true>(A, 0, bias, nullptr, nullptr, g_h, NN);
}

// per-layer: g_hp = h @ Wg[l] (packed A), fused es/ed
__global__ void __launch_bounds__(256) k_mma_h(int mat,
                                               const float* __restrict__ asrc,
                                               const float* __restrict__ adst) {
    mma_gemm_body<false, true, false>(nullptr, mat, nullptr, asrc, adst, g_hp, NN);
}

// ---------------------------------------------------------------------------
// GAT aggregation (warp per destination node, compact CSR). Writes fp32 g_h
// and packed bf16 hi/lo for the next layer's GEMM.
// ---------------------------------------------------------------------------
__global__ void k_gat_aggr(const float* __restrict__ bg) {
    int warp = (blockIdx.x * blockDim.x + threadIdx.x) >> 5;
    int lane = threadIdx.x & 31;
    if (warp >= NN) return;
    const int d = warp;
    const int lo = g_start[d], hi = lo + g_deg[d];
    const float es_d = g_es[d], ed_d = g_ed[d];
    const float e_self = leaky(es_d + ed_d);

    // pass 1: edge scores + segment max
    float m = e_self;
    for (int j = lo + lane; j < hi; j += 32) {
        int s = g_csrc[j];
        float e = leaky(g_es[s] + ed_d);
        g_ee[j] = e;
        m = fmaxf(m, e);
    }
    #pragma unroll
    for (int o = 16; o; o >>= 1) m = fmaxf(m, __shfl_xor_sync(0xffffffffu, m, o));

    const float4* hp4 = (const float4*)g_hp;
    float4* h4 = (float4*)g_h;

    // pass 2: unnormalized weighted sum + z
    float ex_self = expf(e_self - m);
    float z = ex_self;
    float4 v = hp4[(size_t)d * 32 + lane];
    float4 acc;
    acc.x = ex_self * v.x; acc.y = ex_self * v.y;
    acc.z = ex_self * v.z; acc.w = ex_self * v.w;

    for (int j = lo; j < hi; ++j) {
        int s = g_csrc[j];
        float ex = expf(g_ee[j] - m);
        z += ex;
        float4 w = hp4[(size_t)s * 32 + lane];
        acc.x = fmaf(ex, w.x, acc.x);
        acc.y = fmaf(ex, w.y, acc.y);
        acc.z = fmaf(ex, w.z, acc.z);
        acc.w = fmaf(ex, w.w, acc.w);
    }
    const float invz = 1.0f / z;

    float4 b = ((const float4*)bg)[lane];
    float4 hin = h4[(size_t)d * 32 + lane];
    float4 o;
    o.x = fmaxf(fmaf(acc.x, invz, b.x), 0.f) + hin.x;
    o.y = fmaxf(fmaf(acc.y, invz, b.y), 0.f) + hin.y;
    o.z = fmaxf(fmaf(acc.z, invz, b.z), 0.f) + hin.z;
    o.w = fmaxf(fmaf(acc.w, invz, b.w), 0.f) + hin.w;
    h4[(size_t)d * 32 + lane] = o;

    // packed bf16 hi/lo for next GEMM (cols 4*lane .. 4*lane+3 = words 2l,2l+1)
    float hx = bf16_hi_val(o.x), hy = bf16_hi_val(o.y);
    float hz = bf16_hi_val(o.z), hw = bf16_hi_val(o.w);
    uint2 hwd = make_uint2(pack_bf16(o.x, o.y), pack_bf16(o.z, o.w));
    uint2 lwd = make_uint2(pack_bf16(o.x - hx, o.y - hy), pack_bf16(o.z - hz, o.w - hw));
    *(uint2*)&g_ah[(size_t)d * 64 + 2 * lane] = hwd;
    *(uint2*)&g_al[(size_t)d * 64 + 2 * lane] = lwd;
}

// ---------------------------------------------------------------------------
// Fused pool + final projection: block per graph (batch sorted)
// ---------------------------------------------------------------------------
__global__ void k_poolfinal(const void* __restrict__ batch,
                            const float* __restrict__ W2,
                            const float* __restrict__ b2,
                            float* __restrict__ out) {
    __shared__ float ps[128];
    __shared__ int s_lo, s_hi;
    const int g = blockIdx.x;
    const int tid = threadIdx.x;
    if (tid == 0) {
        int lo = 0, hi = NN;
        while (lo < hi) { int mid = (lo + hi) >> 1; if (load_idx(batch, mid) < g) lo = mid + 1; else hi = mid; }
        s_lo = lo;
        lo = 0; hi = NN;
        int g1 = g + 1;
        while (lo < hi) { int mid = (lo + hi) >> 1; if (load_idx(batch, mid) < g1) lo = mid + 1; else hi = mid; }
        s_hi = lo;
    }
    __syncthreads();
    float acc = 0.f;
    for (int i = s_lo; i < s_hi; ++i) acc += g_h[(size_t)i * 128 + tid];
    ps[tid] = acc;
    __syncthreads();
    if (tid < 64) {
        float o = b2[tid];
        #pragma unroll 8
        for (int k = 0; k < 128; ++k)
            o = fmaf(ps[k], W2[k * 64 + tid], o);
        out[g * 64 + tid] = o;
    }
}

// ---------------------------------------------------------------------------
// Launch
// ---------------------------------------------------------------------------
extern "C" void kernel_launch(void* const* d_in, const int* in_sizes, int n_in,
                              void* d_out, int out_size) {
    const float* x     = (const float*)d_in[0];
    const void*  ei    = d_in[1];
    const void*  batch = d_in[2];
    const float* W1    = (const float*)d_in[3];
    const float* b1    = (const float*)d_in[4];
    const float* Wg    = (const float*)d_in[5];
    const float* asrc  = (const float*)d_in[6];
    const float* adst  = (const float*)d_in[7];
    const float* bg    = (const float*)d_in[8];
    const float* W2    = (const float*)d_in[9];
    const float* b2    = (const float*)d_in[10];
    float*       out   = (float*)d_out;

    k_init<<<(NN + 255) / 256, 256>>>((const int*)ei);
    k_wpack<<<(4 * 64 * 128 + 255) / 256, 256>>>(W1, Wg);
    k_hist<<<(EE + 255) / 256, 256>>>(ei);
    k_alloc<<<(NN + 255) / 256, 256>>>();
    k_scatter<<<(EE + 255) / 256, 256>>>(ei);

    const int gemm_blocks = (NN + 127) / 128;
    const int node_warp_blocks = (NN * 32 + 255) / 256;

    k_mma_x<<<gemm_blocks, 256>>>(x, b1);

    for (int l = 0; l < NLAYERS; ++l) {
        k_mma_h<<<gemm_blocks, 256>>>(1 + l, asrc + l * 128, adst + l * 128);
        k_gat_aggr<<<node_warp_blocks, 256>>>(bg + l * 128);
    }

    k_poolfinal<<<NG, 128>>>(batch, W2, b2, out);
}

// round 10
// speedup vs baseline: 1.3021x; 1.3021x over previous
#include <cuda_runtime.h>
#include <cuda_bf16.h>
#include <math.h>
#include <stdint.h>

// Problem constants (match reference)
#define NN      50000
#define EE      600000
#define D_IN    128
#define D_H     128
#define D_OUT   64
#define NLAYERS 3
#define NG      64
#define SLOPE   0.2f

// ---------------------------------------------------------------------------
// Device scratch
// ---------------------------------------------------------------------------
__device__ __align__(16) float g_h [NN * D_H];
__device__ __align__(16) float g_hp[NN * D_H];
__device__ float g_es[NN];
__device__ float g_ed[NN];
__device__ float g_ee[EE];                      // cached per-edge leaky scores
__device__ int   g_deg[NN];
__device__ int   g_start[NN];
__device__ int   g_cur[NN];
__device__ int   g_total;
__device__ int   g_csrc[EE];                    // compact CSR-by-dst source ids
__device__ int   g_is64;

__device__ __forceinline__ float leaky(float x) {
    return x >= 0.f ? x : SLOPE * x;
}

__device__ __forceinline__ int load_idx(const void* p, long long i) {
    return g_is64 ? (int)((const long long*)p)[i] : ((const int*)p)[i];
}

// pack two floats as bf16x2: low half = a (even k), high half = b (odd k)
__device__ __forceinline__ uint32_t pack_bf16(float a, float b) {
    uint32_t r;
    asm("cvt.rn.bf16x2.f32 %0, %1, %2;" : "=r"(r) : "f"(b), "f"(a));
    return r;
}

__device__ __forceinline__ float bf16_hi_val(float x) {
    __nv_bfloat16 h = __float2bfloat16_rn(x);
    return __bfloat162float(h);
}

__device__ __forceinline__ void mma_bf16(float c[4], const uint32_t a[4],
                                         uint32_t b0, uint32_t b1) {
    asm volatile(
        "mma.sync.aligned.m16n8k16.row.col.f32.bf16.bf16.f32 "
        "{%0,%1,%2,%3}, {%4,%5,%6,%7}, {%8,%9}, {%0,%1,%2,%3};\n"
        : "+f"(c[0]), "+f"(c[1]), "+f"(c[2]), "+f"(c[3])
        : "r"(a[0]), "r"(a[1]), "r"(a[2]), "r"(a[3]), "r"(b0), "r"(b1));
}

// ---------------------------------------------------------------------------
// init: zero degrees; parallel index-dtype probe (warp ballot)
// ---------------------------------------------------------------------------
__global__ void k_init(const int* __restrict__ eiw) {
    int i = blockIdx.x * blockDim.x + threadIdx.x;
    if (i < NN) g_deg[i] = 0;
    if (blockIdx.x == 0 && threadIdx.x < 32) {
        int lane = threadIdx.x;
        int nz = (eiw[2 * lane + 1] != 0) | (eiw[2 * (lane + 32) + 1] != 0);
        unsigned bal = __ballot_sync(0xffffffffu, nz);
        if (lane == 0) { g_is64 = (bal == 0u); g_total = 0; }
    }
}

// ---------------------------------------------------------------------------
// Compact CSR build: hist -> alloc -> scatter
// ---------------------------------------------------------------------------
__global__ void k_hist(const void* __restrict__ ei) {
    int e = blockIdx.x * blockDim.x + threadIdx.x;
    if (e < EE) {
        int d = load_idx(ei, (long long)EE + e);
        if ((unsigned)d < NN) atomicAdd(&g_deg[d], 1);
    }
}

__global__ void k_alloc() {
    int i = blockIdx.x * blockDim.x + threadIdx.x;
    if (i < NN) {
        int dg = g_deg[i];
        int st = atomicAdd(&g_total, dg);
        g_start[i] = st;
        g_cur[i]   = st;
    }
}

__global__ void k_scatter(const void* __restrict__ ei) {
    int e = blockIdx.x * blockDim.x + threadIdx.x;
    if (e < EE) {
        int s = load_idx(ei, e);
        int d = load_idx(ei, (long long)EE + e);
        if ((unsigned)d < NN && (unsigned)s < NN) {
            int pos = atomicAdd(&g_cur[d], 1);
            g_csrc[pos] = s;
        }
    }
}

// ---------------------------------------------------------------------------
// 3xBF16 tensor-core GEMM: C[M,128] = A[M,128] @ B[128,128] (+bias)
// Block 128x128, 256 threads (8 warps, 2x4), warp tile 64x32, BK=16,
// DOUBLE-BUFFERED smem staging: per chunk, next chunk's LDGs issue before the
// MMAs on the current buffer (load latency hidden), then convert+STS, 1 sync.
// Optional fused epilogue: es/ed row-dots with asrc/adst.
// ---------------------------------------------------------------------------
#define PAD 136

template <bool FUSE_ESED>
__device__ __forceinline__ void mma_gemm_body(const float* __restrict__ A,
                                              const float* __restrict__ B,
                                              const float* __restrict__ bias,
                                              const float* __restrict__ asrc,
                                              const float* __restrict__ adst,
                                              float* __restrict__ C, int M) {
    __shared__ uint32_t Ah[2][8][PAD], Al[2][8][PAD];   // [buf][k-pair][m]
    __shared__ uint32_t Bh[2][8][PAD], Bl[2][8][PAD];   // [buf][k-pair][n]
    __shared__ float es_s[128], ed_s[128];

    const int tid  = threadIdx.x;
    const int warp = tid >> 5, lane = tid & 31;
    const int wm = warp >> 2, wn = warp & 3;
    const int gid = lane >> 2, tig = lane & 3;
    const int brow = blockIdx.x * 128;

    if (FUSE_ESED && tid < 128) { es_s[tid] = 0.f; ed_s[tid] = 0.f; }

    const int a_r  = tid & 63;
    const int a_kq = (tid >> 6) * 4;   // k offset within chunk (0 or 4)
    const int b_bp = tid >> 5;         // 0..7 (k-pair row)
    const int b_n  = (tid & 31) * 4;

    float acc[4][4][4];
    #pragma unroll
    for (int mt = 0; mt < 4; mt++)
        #pragma unroll
        for (int nt = 0; nt < 4; nt++)
            #pragma unroll
            for (int c = 0; c < 4; c++) acc[mt][nt][c] = 0.f;

    float4 av0, av1, bv0, bv1;   // prefetch registers

    // --- chunk loader (global -> registers)
    auto load_chunk = [&](int kc) {
        int g0 = brow + a_r;
        int g1 = brow + a_r + 64;
        av0 = (g0 < M) ? *(const float4*)&A[(size_t)g0 * 128 + kc + a_kq]
                       : make_float4(0.f, 0.f, 0.f, 0.f);
        av1 = (g1 < M) ? *(const float4*)&A[(size_t)g1 * 128 + kc + a_kq]
                       : make_float4(0.f, 0.f, 0.f, 0.f);
        const float* B0 = &B[(size_t)(kc + 2 * b_bp) * 128 + b_n];
        bv0 = *(const float4*)B0;
        bv1 = *(const float4*)(B0 + 128);
    };

    // --- convert + store (registers -> smem buffer)
    auto store_chunk = [&](int buf) {
        #pragma unroll
        for (int p = 0; p < 2; p++) {
            float4 v = p ? av1 : av0;
            int r = a_r + 64 * p;
            float h0 = bf16_hi_val(v.x), h1 = bf16_hi_val(v.y);
            float h2 = bf16_hi_val(v.z), h3 = bf16_hi_val(v.w);
            Ah[buf][a_kq / 2][r]     = pack_bf16(v.x, v.y);
            Ah[buf][a_kq / 2 + 1][r] = pack_bf16(v.z, v.w);
            Al[buf][a_kq / 2][r]     = pack_bf16(v.x - h0, v.y - h1);
            Al[buf][a_kq / 2 + 1][r] = pack_bf16(v.z - h2, v.w - h3);
        }
        float f0[4] = {bv0.x, bv0.y, bv0.z, bv0.w};
        float f1[4] = {bv1.x, bv1.y, bv1.z, bv1.w};
        uint4 hq, lq;
        uint32_t* hp_ = (uint32_t*)&hq;
        uint32_t* lp_ = (uint32_t*)&lq;
        #pragma unroll
        for (int i = 0; i < 4; i++) {
            float h0 = bf16_hi_val(f0[i]), l0 = f0[i] - h0;
            float h1 = bf16_hi_val(f1[i]), l1 = f1[i] - h1;
            hp_[i] = pack_bf16(h0, h1);
            lp_[i] = pack_bf16(l0, l1);
        }
        *(uint4*)&Bh[buf][b_bp][b_n] = hq;
        *(uint4*)&Bl[buf][b_bp][b_n] = lq;
    };

    // prologue: chunk 0 into buffer 0
    load_chunk(0);
    store_chunk(0);
    __syncthreads();

    #pragma unroll 1
    for (int c = 0; c < 8; c++) {
        const int cur = c & 1;
        if (c < 7) load_chunk((c + 1) * 16);   // LDGs issue before MMAs

        // MMAs on buffer `cur`
        {
            uint32_t ah[4][4], al[4][4];
            #pragma unroll
            for (int mt = 0; mt < 4; mt++) {
                int m0 = wm * 64 + mt * 16 + gid;
                ah[mt][0] = Ah[cur][tig][m0];     ah[mt][1] = Ah[cur][tig][m0 + 8];
                ah[mt][2] = Ah[cur][tig + 4][m0]; ah[mt][3] = Ah[cur][tig + 4][m0 + 8];
                al[mt][0] = Al[cur][tig][m0];     al[mt][1] = Al[cur][tig][m0 + 8];
                al[mt][2] = Al[cur][tig + 4][m0]; al[mt][3] = Al[cur][tig + 4][m0 + 8];
            }
            #pragma unroll
            for (int nt = 0; nt < 4; nt++) {
                int n0 = wn * 32 + nt * 8 + gid;
                uint32_t bh0 = Bh[cur][tig][n0], bh1 = Bh[cur][tig + 4][n0];
                uint32_t bl0 = Bl[cur][tig][n0], bl1 = Bl[cur][tig + 4][n0];
                #pragma unroll
                for (int mt = 0; mt < 4; mt++) {
                    mma_bf16(acc[mt][nt], ah[mt], bh0, bh1);
                    mma_bf16(acc[mt][nt], ah[mt], bl0, bl1);
                    mma_bf16(acc[mt][nt], al[mt], bh0, bh1);
                }
            }
        }

        if (c < 7) store_chunk(cur ^ 1);
        __syncthreads();
    }

    float as_v[4][2], ad_v[4][2];
    if (FUSE_ESED) {
        #pragma unroll
        for (int nt = 0; nt < 4; nt++) {
            int c0 = wn * 32 + nt * 8 + 2 * tig;
            as_v[nt][0] = asrc[c0]; as_v[nt][1] = asrc[c0 + 1];
            ad_v[nt][0] = adst[c0]; ad_v[nt][1] = adst[c0 + 1];
        }
    }

    #pragma unroll
    for (int mt = 0; mt < 4; mt++) {
        int r0 = brow + wm * 64 + mt * 16 + gid;
        float pe0 = 0.f, pe1 = 0.f, pd0 = 0.f, pd1 = 0.f;
        #pragma unroll
        for (int nt = 0; nt < 4; nt++) {
            int c0 = wn * 32 + nt * 8 + 2 * tig;
            float b0v = bias ? bias[c0]     : 0.f;
            float b1v = bias ? bias[c0 + 1] : 0.f;
            float v00 = acc[mt][nt][0] + b0v, v01 = acc[mt][nt][1] + b1v;
            float v10 = acc[mt][nt][2] + b0v, v11 = acc[mt][nt][3] + b1v;
            if (r0 < M)     *(float2*)&C[(size_t)r0 * 128 + c0]       = make_float2(v00, v01);
            if (r0 + 8 < M) *(float2*)&C[(size_t)(r0 + 8) * 128 + c0] = make_float2(v10, v11);
            if (FUSE_ESED) {
                pe0 += v00 * as_v[nt][0] + v01 * as_v[nt][1];
                pe1 += v10 * as_v[nt][0] + v11 * as_v[nt][1];
                pd0 += v00 * ad_v[nt][0] + v01 * ad_v[nt][1];
                pd1 += v10 * ad_v[nt][0] + v11 * ad_v[nt][1];
            }
        }
        if (FUSE_ESED) {
            #pragma unroll
            for (int o = 1; o <= 2; o <<= 1) {
                pe0 += __shfl_xor_sync(0xffffffffu, pe0, o);
                pe1 += __shfl_xor_sync(0xffffffffu, pe1, o);
                pd0 += __shfl_xor_sync(0xffffffffu, pd0, o);
                pd1 += __shfl_xor_sync(0xffffffffu, pd1, o);
            }
            if (tig == 0) {
                int lr = wm * 64 + mt * 16 + gid;
                atomicAdd(&es_s[lr], pe0);     atomicAdd(&es_s[lr + 8], pe1);
                atomicAdd(&ed_s[lr], pd0);     atomicAdd(&ed_s[lr + 8], pd1);
            }
        }
    }

    if (FUSE_ESED) {
        __syncthreads();
        if (tid < 128 && brow + tid < M) {
            g_es[brow + tid] = es_s[tid];
            g_ed[brow + tid] = ed_s[tid];
        }
    }
}

__global__ void __launch_bounds__(256, 2) k_mma_x(const float* __restrict__ A,
                                                  const float* __restrict__ B,
                                                  const float* __restrict__ bias) {
    mma_gemm_body<false>(A, B, bias, nullptr, nullptr, g_h, NN);
}

__global__ void __launch_bounds__(256, 2) k_mma_h(const float* __restrict__ B,
                                                  const float* __restrict__ asrc,
                                                  const float* __restrict__ adst) {
    mma_gemm_body<true>(g_h, B, nullptr, asrc, adst, g_hp, NN);
}

// ---------------------------------------------------------------------------
// GAT aggregation (warp per destination node, compact CSR)
// ---------------------------------------------------------------------------
__global__ void k_gat_aggr(const float* __restrict__ bg) {
    int warp = (blockIdx.x * blockDim.x + threadIdx.x) >> 5;
    int lane = threadIdx.x & 31;
    if (warp >= NN) return;
    const int d = warp;
    const int lo = g_start[d], hi = lo + g_deg[d];
    const float es_d = g_es[d], ed_d = g_ed[d];
    const float e_self = leaky(es_d + ed_d);

    // pass 1: edge scores + segment max
    float m = e_self;
    for (int j = lo + lane; j < hi; j += 32) {
        int s = g_csrc[j];
        float e = leaky(g_es[s] + ed_d);
        g_ee[j] = e;
        m = fmaxf(m, e);
    }
    #pragma unroll
    for (int o = 16; o; o >>= 1) m = fmaxf(m, __shfl_xor_sync(0xffffffffu, m, o));

    const float4* hp4 = (const float4*)g_hp;
    float4* h4 = (float4*)g_h;

    // pass 2: unnormalized weighted sum + z
    float ex_self = expf(e_self - m);
    float z = ex_self;
    float4 v = hp4[(size_t)d * 32 + lane];
    float4 acc;
    acc.x = ex_self * v.x; acc.y = ex_self * v.y;
    acc.z = ex_self * v.z; acc.w = ex_self * v.w;

    for (int j = lo; j < hi; ++j) {
        int s = g_csrc[j];
        float ex = expf(g_ee[j] - m);
        z += ex;
        float4 w = hp4[(size_t)s * 32 + lane];
        acc.x = fmaf(ex, w.x, acc.x);
        acc.y = fmaf(ex, w.y, acc.y);
        acc.z = fmaf(ex, w.z, acc.z);
        acc.w = fmaf(ex, w.w, acc.w);
    }
    const float invz = 1.0f / z;

    float4 b = ((const float4*)bg)[lane];
    float4 hin = h4[(size_t)d * 32 + lane];
    float4 o;
    o.x = fmaxf(fmaf(acc.x, invz, b.x), 0.f) + hin.x;
    o.y = fmaxf(fmaf(acc.y, invz, b.y), 0.f) + hin.y;
    o.z = fmaxf(fmaf(acc.z, invz, b.z), 0.f) + hin.z;
    o.w = fmaxf(fmaf(acc.w, invz, b.w), 0.f) + hin.w;
    h4[(size_t)d * 32 + lane] = o;
}

// ---------------------------------------------------------------------------
// Fused pool + final projection: block per graph (batch sorted)
// ---------------------------------------------------------------------------
__global__ void k_poolfinal(const void* __restrict__ batch,
                            const float* __restrict__ W2,
                            const float* __restrict__ b2,
                            float* __restrict__ out) {
    __shared__ float ps[128];
    __shared__ int s_lo, s_hi;
    const int g = blockIdx.x;
    const int tid = threadIdx.x;
    if (tid == 0) {
        int lo = 0, hi = NN;
        while (lo < hi) { int mid = (lo + hi) >> 1; if (load_idx(batch, mid) < g) lo = mid + 1; else hi = mid; }
        s_lo = lo;
        lo = 0; hi = NN;
        int g1 = g + 1;
        while (lo < hi) { int mid = (lo + hi) >> 1; if (load_idx(batch, mid) < g1) lo = mid + 1; else hi = mid; }
        s_hi = lo;
    }
    __syncthreads();
    float acc = 0.f;
    for (int i = s_lo; i < s_hi; ++i) acc += g_h[(size_t)i * 128 + tid];
    ps[tid] = acc;
    __syncthreads();
    if (tid < 64) {
        float o = b2[tid];
        #pragma unroll 8
        for (int k = 0; k < 128; ++k)
            o = fmaf(ps[k], W2[k * 64 + tid], o);
        out[g * 64 + tid] = o;
    }
}

// ---------------------------------------------------------------------------
// Launch
// ---------------------------------------------------------------------------
extern "C" void kernel_launch(void* const* d_in, const int* in_sizes, int n_in,
                              void* d_out, int out_size) {
    const float* x     = (const float*)d_in[0];
    const void*  ei    = d_in[1];
    const void*  batch = d_in[2];
    const float* W1    = (const float*)d_in[3];
    const float* b1    = (const float*)d_in[4];
    const float* Wg    = (const float*)d_in[5];
    const float* asrc  = (const float*)d_in[6];
    const float* adst  = (const float*)d_in[7];
    const float* bg    = (const float*)d_in[8];
    const float* W2    = (const float*)d_in[9];
    const float* b2    = (const float*)d_in[10];
    float*       out   = (float*)d_out;

    k_init<<<(NN + 255) / 256, 256>>>((const int*)ei);
    k_hist<<<(EE + 255) / 256, 256>>>(ei);
    k_alloc<<<(NN + 255) / 256, 256>>>();
    k_scatter<<<(EE + 255) / 256, 256>>>(ei);

    const int gemm_blocks = (NN + 127) / 128;
    const int node_warp_blocks = (NN * 32 + 255) / 256;

    k_mma_x<<<gemm_blocks, 256>>>(x, W1, b1);

    for (int l = 0; l < NLAYERS; ++l) {
        k_mma_h<<<gemm_blocks, 256>>>(Wg + (size_t)l * 128 * 128,
                                      asrc + l * 128, adst + l * 128);
        k_gat_aggr<<<node_warp_blocks, 256>>>(bg + l * 128);
    }

    k_poolfinal<<<NG, 128>>>(batch, W2, b2, out);
}

// round 11
// speedup vs baseline: 1.3103x; 1.0063x over previous
#include <cuda_runtime.h>
#include <cuda_bf16.h>
#include <cuda_fp16.h>
#include <math.h>
#include <stdint.h>

// Problem constants (match reference)
#define NN      50000
#define EE      600000
#define D_IN    128
#define D_H     128
#define D_OUT   64
#define NLAYERS 3
#define NG      64
#define SLOPE   0.2f

// ---------------------------------------------------------------------------
// Device scratch
// ---------------------------------------------------------------------------
__device__ __align__(16) float  g_h  [NN * D_H];   // fp32 features (residual/pool)
__device__ __align__(16) __half g_hpf[NN * D_H];   // fp16 h@W (aggregation gathers)
__device__ float g_es[NN];
__device__ float g_ed[NN];
__device__ int   g_deg[NN];
__device__ int   g_start[NN];
__device__ int   g_cur[NN];
__device__ int   g_total;
__device__ int   g_csrc[EE];                       // compact CSR-by-dst source ids
__device__ int   g_is64;

__device__ __forceinline__ float leaky(float x) {
    return x >= 0.f ? x : SLOPE * x;
}

__device__ __forceinline__ int load_idx(const void* p, long long i) {
    return g_is64 ? (int)((const long long*)p)[i] : ((const int*)p)[i];
}

// pack two floats as bf16x2: low half = a (even k), high half = b (odd k)
__device__ __forceinline__ uint32_t pack_bf16(float a, float b) {
    uint32_t r;
    asm("cvt.rn.bf16x2.f32 %0, %1, %2;" : "=r"(r) : "f"(b), "f"(a));
    return r;
}

__device__ __forceinline__ float bf16_hi_val(float x) {
    __nv_bfloat16 h = __float2bfloat16_rn(x);
    return __bfloat162float(h);
}

__device__ __forceinline__ void mma_bf16(float c[4], const uint32_t a[4],
                                         uint32_t b0, uint32_t b1) {
    asm volatile(
        "mma.sync.aligned.m16n8k16.row.col.f32.bf16.bf16.f32 "
        "{%0,%1,%2,%3}, {%4,%5,%6,%7}, {%8,%9}, {%0,%1,%2,%3};\n"
        : "+f"(c[0]), "+f"(c[1]), "+f"(c[2]), "+f"(c[3])
        : "r"(a[0]), "r"(a[1]), "r"(a[2]), "r"(a[3]), "r"(b0), "r"(b1));
}

// ---------------------------------------------------------------------------
// init: zero degrees; parallel index-dtype probe (warp ballot)
// ---------------------------------------------------------------------------
__global__ void k_init(const int* __restrict__ eiw) {
    int i = blockIdx.x * blockDim.x + threadIdx.x;
    if (i < NN) g_deg[i] = 0;
    if (blockIdx.x == 0 && threadIdx.x < 32) {
        int lane = threadIdx.x;
        int nz = (eiw[2 * lane + 1] != 0) | (eiw[2 * (lane + 32) + 1] != 0);
        unsigned bal = __ballot_sync(0xffffffffu, nz);
        if (lane == 0) { g_is64 = (bal == 0u); g_total = 0; }
    }
}

// ---------------------------------------------------------------------------
// Compact CSR build: hist -> alloc -> scatter
// ---------------------------------------------------------------------------
__global__ void k_hist(const void* __restrict__ ei) {
    int e = blockIdx.x * blockDim.x + threadIdx.x;
    if (e < EE) {
        int d = load_idx(ei, (long long)EE + e);
        if ((unsigned)d < NN) atomicAdd(&g_deg[d], 1);
    }
}

__global__ void k_alloc() {
    int i = blockIdx.x * blockDim.x + threadIdx.x;
    if (i < NN) {
        int dg = g_deg[i];
        int st = atomicAdd(&g_total, dg);
        g_start[i] = st;
        g_cur[i]   = st;
    }
}

__global__ void k_scatter(const void* __restrict__ ei) {
    int e = blockIdx.x * blockDim.x + threadIdx.x;
    if (e < EE) {
        int s = load_idx(ei, e);
        int d = load_idx(ei, (long long)EE + e);
        if ((unsigned)d < NN && (unsigned)s < NN) {
            int pos = atomicAdd(&g_cur[d], 1);
            g_csrc[pos] = s;
        }
    }
}

// ---------------------------------------------------------------------------
// 3xBF16 tensor-core GEMM: C[M,128] = A[M,128] @ B[128,128] (+bias)
// Block 128x128, 256 threads (8 warps, 2x4), warp tile 64x32, BK=16,
// double-buffered smem staging (R10).
// HALF_OUT: write fp16 into g_hpf (aggregation input); else fp32 into C.
// FUSE_ESED: epilogue computes es/ed row-dots (from exact fp32 accumulators).
// ---------------------------------------------------------------------------
#define PAD 136

template <bool FUSE_ESED, bool HALF_OUT>
__device__ __forceinline__ void mma_gemm_body(const float* __restrict__ A,
                                              const float* __restrict__ B,
                                              const float* __restrict__ bias,
                                              const float* __restrict__ asrc,
                                              const float* __restrict__ adst,
                                              float* __restrict__ C, int M) {
    __shared__ uint32_t Ah[2][8][PAD], Al[2][8][PAD];   // [buf][k-pair][m]
    __shared__ uint32_t Bh[2][8][PAD], Bl[2][8][PAD];   // [buf][k-pair][n]
    __shared__ float es_s[128], ed_s[128];

    const int tid  = threadIdx.x;
    const int warp = tid >> 5, lane = tid & 31;
    const int wm = warp >> 2, wn = warp & 3;
    const int gid = lane >> 2, tig = lane & 3;
    const int brow = blockIdx.x * 128;

    if (FUSE_ESED && tid < 128) { es_s[tid] = 0.f; ed_s[tid] = 0.f; }

    const int a_r  = tid & 63;
    const int a_kq = (tid >> 6) * 4;   // k offset within chunk (0 or 4)
    const int b_bp = tid >> 5;         // 0..7 (k-pair row)
    const int b_n  = (tid & 31) * 4;

    float acc[4][4][4];
    #pragma unroll
    for (int mt = 0; mt < 4; mt++)
        #pragma unroll
        for (int nt = 0; nt < 4; nt++)
            #pragma unroll
            for (int c = 0; c < 4; c++) acc[mt][nt][c] = 0.f;

    float4 av0, av1, bv0, bv1;   // prefetch registers

    auto load_chunk = [&](int kc) {
        int g0 = brow + a_r;
        int g1 = brow + a_r + 64;
        av0 = (g0 < M) ? *(const float4*)&A[(size_t)g0 * 128 + kc + a_kq]
                       : make_float4(0.f, 0.f, 0.f, 0.f);
        av1 = (g1 < M) ? *(const float4*)&A[(size_t)g1 * 128 + kc + a_kq]
                       : make_float4(0.f, 0.f, 0.f, 0.f);
        const float* B0 = &B[(size_t)(kc + 2 * b_bp) * 128 + b_n];
        bv0 = *(const float4*)B0;
        bv1 = *(const float4*)(B0 + 128);
    };

    auto store_chunk = [&](int buf) {
        #pragma unroll
        for (int p = 0; p < 2; p++) {
            float4 v = p ? av1 : av0;
            int r = a_r + 64 * p;
            float h0 = bf16_hi_val(v.x), h1 = bf16_hi_val(v.y);
            float h2 = bf16_hi_val(v.z), h3 = bf16_hi_val(v.w);
            Ah[buf][a_kq / 2][r]     = pack_bf16(v.x, v.y);
            Ah[buf][a_kq / 2 + 1][r] = pack_bf16(v.z, v.w);
            Al[buf][a_kq / 2][r]     = pack_bf16(v.x - h0, v.y - h1);
            Al[buf][a_kq / 2 + 1][r] = pack_bf16(v.z - h2, v.w - h3);
        }
        float f0[4] = {bv0.x, bv0.y, bv0.z, bv0.w};
        float f1[4] = {bv1.x, bv1.y, bv1.z, bv1.w};
        uint4 hq, lq;
        uint32_t* hp_ = (uint32_t*)&hq;
        uint32_t* lp_ = (uint32_t*)&lq;
        #pragma unroll
        for (int i = 0; i < 4; i++) {
            float h0 = bf16_hi_val(f0[i]), l0 = f0[i] - h0;
            float h1 = bf16_hi_val(f1[i]), l1 = f1[i] - h1;
            hp_[i] = pack_bf16(h0, h1);
            lp_[i] = pack_bf16(l0, l1);
        }
        *(uint4*)&Bh[buf][b_bp][b_n] = hq;
        *(uint4*)&Bl[buf][b_bp][b_n] = lq;
    };

    load_chunk(0);
    store_chunk(0);
    __syncthreads();

    #pragma unroll 1
    for (int c = 0; c < 8; c++) {
        const int cur = c & 1;
        if (c < 7) load_chunk((c + 1) * 16);

        {
            uint32_t ah[4][4], al[4][4];
            #pragma unroll
            for (int mt = 0; mt < 4; mt++) {
                int m0 = wm * 64 + mt * 16 + gid;
                ah[mt][0] = Ah[cur][tig][m0];     ah[mt][1] = Ah[cur][tig][m0 + 8];
                ah[mt][2] = Ah[cur][tig + 4][m0]; ah[mt][3] = Ah[cur][tig + 4][m0 + 8];
                al[mt][0] = Al[cur][tig][m0];     al[mt][1] = Al[cur][tig][m0 + 8];
                al[mt][2] = Al[cur][tig + 4][m0]; al[mt][3] = Al[cur][tig + 4][m0 + 8];
            }
            #pragma unroll
            for (int nt = 0; nt < 4; nt++) {
                int n0 = wn * 32 + nt * 8 + gid;
                uint32_t bh0 = Bh[cur][tig][n0], bh1 = Bh[cur][tig + 4][n0];
                uint32_t bl0 = Bl[cur][tig][n0], bl1 = Bl[cur][tig + 4][n0];
                #pragma unroll
                for (int mt = 0; mt < 4; mt++) {
                    mma_bf16(acc[mt][nt], ah[mt], bh0, bh1);
                    mma_bf16(acc[mt][nt], ah[mt], bl0, bl1);
                    mma_bf16(acc[mt][nt], al[mt], bh0, bh1);
                }
            }
        }

        if (c < 7) store_chunk(cur ^ 1);
        __syncthreads();
    }

    float as_v[4][2], ad_v[4][2];
    if (FUSE_ESED) {
        #pragma unroll
        for (int nt = 0; nt < 4; nt++) {
            int c0 = wn * 32 + nt * 8 + 2 * tig;
            as_v[nt][0] = asrc[c0]; as_v[nt][1] = asrc[c0 + 1];
            ad_v[nt][0] = adst[c0]; ad_v[nt][1] = adst[c0 + 1];
        }
    }

    #pragma unroll
    for (int mt = 0; mt < 4; mt++) {
        int r0 = brow + wm * 64 + mt * 16 + gid;
        float pe0 = 0.f, pe1 = 0.f, pd0 = 0.f, pd1 = 0.f;
        #pragma unroll
        for (int nt = 0; nt < 4; nt++) {
            int c0 = wn * 32 + nt * 8 + 2 * tig;
            float b0v = bias ? bias[c0]     : 0.f;
            float b1v = bias ? bias[c0 + 1] : 0.f;
            float v00 = acc[mt][nt][0] + b0v, v01 = acc[mt][nt][1] + b1v;
            float v10 = acc[mt][nt][2] + b0v, v11 = acc[mt][nt][3] + b1v;
            if (HALF_OUT) {
                if (r0 < M)     *(half2*)&g_hpf[(size_t)r0 * 128 + c0]       = __floats2half2_rn(v00, v01);
                if (r0 + 8 < M) *(half2*)&g_hpf[(size_t)(r0 + 8) * 128 + c0] = __floats2half2_rn(v10, v11);
            } else {
                if (r0 < M)     *(float2*)&C[(size_t)r0 * 128 + c0]       = make_float2(v00, v01);
                if (r0 + 8 < M) *(float2*)&C[(size_t)(r0 + 8) * 128 + c0] = make_float2(v10, v11);
            }
            if (FUSE_ESED) {
                pe0 += v00 * as_v[nt][0] + v01 * as_v[nt][1];
                pe1 += v10 * as_v[nt][0] + v11 * as_v[nt][1];
                pd0 += v00 * ad_v[nt][0] + v01 * ad_v[nt][1];
                pd1 += v10 * ad_v[nt][0] + v11 * ad_v[nt][1];
            }
        }
        if (FUSE_ESED) {
            #pragma unroll
            for (int o = 1; o <= 2; o <<= 1) {
                pe0 += __shfl_xor_sync(0xffffffffu, pe0, o);
                pe1 += __shfl_xor_sync(0xffffffffu, pe1, o);
                pd0 += __shfl_xor_sync(0xffffffffu, pd0, o);
                pd1 += __shfl_xor_sync(0xffffffffu, pd1, o);
            }
            if (tig == 0) {
                int lr = wm * 64 + mt * 16 + gid;
                atomicAdd(&es_s[lr], pe0);     atomicAdd(&es_s[lr + 8], pe1);
                atomicAdd(&ed_s[lr], pd0);     atomicAdd(&ed_s[lr + 8], pd1);
            }
        }
    }

    if (FUSE_ESED) {
        __syncthreads();
        if (tid < 128 && brow + tid < M) {
            g_es[brow + tid] = es_s[tid];
            g_ed[brow + tid] = ed_s[tid];
        }
    }
}

// mlp1: g_h = x @ W1 + b1 (fp32 out)
__global__ void __launch_bounds__(256, 2) k_mma_x(const float* __restrict__ A,
                                                  const float* __restrict__ B,
                                                  const float* __restrict__ bias) {
    mma_gemm_body<false, false>(A, B, bias, nullptr, nullptr, g_h, NN);
}

// per-layer: g_hpf = fp16(h @ Wg[l]), fused exact es/ed
__global__ void __launch_bounds__(256, 2) k_mma_h(const float* __restrict__ B,
                                                  const float* __restrict__ asrc,
                                                  const float* __restrict__ adst) {
    mma_gemm_body<true, true>(g_h, B, nullptr, asrc, adst, nullptr, NN);
}

// ---------------------------------------------------------------------------
// GAT aggregation (warp per destination node, compact CSR) — SINGLE PASS:
// softmax without max-shift (logits are O(10); fp32 exp overflows at 88),
// fp16 feature gather (256 B/edge), fp32 accumulation, exact fp32 logits.
// ---------------------------------------------------------------------------
__global__ void k_gat_aggr(const float* __restrict__ bg) {
    int warp = (blockIdx.x * blockDim.x + threadIdx.x) >> 5;
    int lane = threadIdx.x & 31;
    if (warp >= NN) return;
    const int d = warp;
    const int lo = g_start[d], hi = lo + g_deg[d];
    const float ed_d = g_ed[d];
    const float e_self = leaky(g_es[d] + ed_d);

    // self-loop
    float ex_self = expf(e_self);
    float z = ex_self;
    uint2 sv = *(const uint2*)&g_hpf[(size_t)d * 128 + 4 * lane];
    float2 s0 = __half22float2(*(half2*)&sv.x);
    float2 s1 = __half22float2(*(half2*)&sv.y);
    float ax = ex_self * s0.x, ay = ex_self * s0.y;
    float az = ex_self * s1.x, aw = ex_self * s1.y;

    // single pass over in-edges
    for (int j = lo; j < hi; ++j) {
        int s = g_csrc[j];                                  // broadcast
        float ex = expf(leaky(g_es[s] + ed_d));             // broadcast es load
        z += ex;
        uint2 wv = *(const uint2*)&g_hpf[(size_t)s * 128 + 4 * lane];
        float2 w0 = __half22float2(*(half2*)&wv.x);
        float2 w1 = __half22float2(*(half2*)&wv.y);
        ax = fmaf(ex, w0.x, ax);
        ay = fmaf(ex, w0.y, ay);
        az = fmaf(ex, w1.x, az);
        aw = fmaf(ex, w1.y, aw);
    }
    const float invz = 1.0f / z;

    float4* h4 = (float4*)g_h;
    float4 b = ((const float4*)bg)[lane];
    float4 hin = h4[(size_t)d * 32 + lane];
    float4 o;
    o.x = fmaxf(fmaf(ax, invz, b.x), 0.f) + hin.x;
    o.y = fmaxf(fmaf(ay, invz, b.y), 0.f) + hin.y;
    o.z = fmaxf(fmaf(az, invz, b.z), 0.f) + hin.z;
    o.w = fmaxf(fmaf(aw, invz, b.w), 0.f) + hin.w;
    h4[(size_t)d * 32 + lane] = o;
}

// ---------------------------------------------------------------------------
// Fused pool + final projection: block per graph (batch sorted)
// ---------------------------------------------------------------------------
__global__ void k_poolfinal(const void* __restrict__ batch,
                            const float* __restrict__ W2,
                            const float* __restrict__ b2,
                            float* __restrict__ out) {
    __shared__ float ps[128];
    __shared__ int s_lo, s_hi;
    const int g = blockIdx.x;
    const int tid = threadIdx.x;
    if (tid == 0) {
        int lo = 0, hi = NN;
        while (lo < hi) { int mid = (lo + hi) >> 1; if (load_idx(batch, mid) < g) lo = mid + 1; else hi = mid; }
        s_lo = lo;
        lo = 0; hi = NN;
        int g1 = g + 1;
        while (lo < hi) { int mid = (lo + hi) >> 1; if (load_idx(batch, mid) < g1) lo = mid + 1; else hi = mid; }
        s_hi = lo;
    }
    __syncthreads();
    float acc = 0.f;
    for (int i = s_lo; i < s_hi; ++i) acc += g_h[(size_t)i * 128 + tid];
    ps[tid] = acc;
    __syncthreads();
    if (tid < 64) {
        float o = b2[tid];
        #pragma unroll 8
        for (int k = 0; k < 128; ++k)
            o = fmaf(ps[k], W2[k * 64 + tid], o);
        out[g * 64 + tid] = o;
    }
}

// ---------------------------------------------------------------------------
// Launch
// ---------------------------------------------------------------------------
extern "C" void kernel_launch(void* const* d_in, const int* in_sizes, int n_in,
                              void* d_out, int out_size) {
    const float* x     = (const float*)d_in[0];
    const void*  ei    = d_in[1];
    const void*  batch = d_in[2];
    const float* W1    = (const float*)d_in[3];
    const float* b1    = (const float*)d_in[4];
    const float* Wg    = (const float*)d_in[5];
    const float* asrc  = (const float*)d_in[6];
    const float* adst  = (const float*)d_in[7];
    const float* bg    = (const float*)d_in[8];
    const float* W2    = (const float*)d_in[9];
    const float* b2    = (const float*)d_in[10];
    float*       out   = (float*)d_out;

    k_init<<<(NN + 255) / 256, 256>>>((const int*)ei);
    k_hist<<<(EE + 255) / 256, 256>>>(ei);
    k_alloc<<<(NN + 255) / 256, 256>>>();
    k_scatter<<<(EE + 255) / 256, 256>>>(ei);

    const int gemm_blocks = (NN + 127) / 128;
    const int node_warp_blocks = (NN * 32 + 255) / 256;

    k_mma_x<<<gemm_blocks, 256>>>(x, W1, b1);

    for (int l = 0; l < NLAYERS; ++l) {
        k_mma_h<<<gemm_blocks, 256>>>(Wg + (size_t)l * 128 * 128,
                                      asrc + l * 128, adst + l * 128);
        k_gat_aggr<<<node_warp_blocks, 256>>>(bg + l * 128);
    }

    k_poolfinal<<<NG, 128>>>(batch, W2, b2, out);
}

// round 12
// speedup vs baseline: 1.3217x; 1.0087x over previous
#include <cuda_runtime.h>
#include <cuda_bf16.h>
#include <cuda_fp16.h>
#include <math.h>
#include <stdint.h>

// Problem constants (match reference)
#define NN      50000
#define EE      600000
#define D_IN    128
#define D_H     128
#define D_OUT   64
#define NLAYERS 3
#define NG      64
#define SLOPE   0.2f

// ---------------------------------------------------------------------------
// Device scratch
// ---------------------------------------------------------------------------
__device__ __align__(16) float  g_h  [NN * D_H];   // fp32 features (residual/pool)
__device__ __align__(16) __half g_hpf[NN * D_H];   // fp16 h@W (aggregation gathers)
__device__ float g_es[NN];
__device__ float g_ed[NN];
__device__ int   g_deg[NN];
__device__ int   g_start[NN];
__device__ int   g_cur[NN];
__device__ int   g_total;
__device__ int   g_csrc[EE];                       // compact CSR-by-dst source ids
__device__ int   g_is64;

__device__ __forceinline__ float leaky(float x) {
    return x >= 0.f ? x : SLOPE * x;
}

__device__ __forceinline__ int load_idx(const void* p, long long i) {
    return g_is64 ? (int)((const long long*)p)[i] : ((const int*)p)[i];
}

// pack two floats as bf16x2: low half = a (even k), high half = b (odd k)
__device__ __forceinline__ uint32_t pack_bf16(float a, float b) {
    uint32_t r;
    asm("cvt.rn.bf16x2.f32 %0, %1, %2;" : "=r"(r) : "f"(b), "f"(a));
    return r;
}

__device__ __forceinline__ float bf16_hi_val(float x) {
    __nv_bfloat16 h = __float2bfloat16_rn(x);
    return __bfloat162float(h);
}

__device__ __forceinline__ void mma_bf16(float c[4], const uint32_t a[4],
                                         uint32_t b0, uint32_t b1) {
    asm volatile(
        "mma.sync.aligned.m16n8k16.row.col.f32.bf16.bf16.f32 "
        "{%0,%1,%2,%3}, {%4,%5,%6,%7}, {%8,%9}, {%0,%1,%2,%3};\n"
        : "+f"(c[0]), "+f"(c[1]), "+f"(c[2]), "+f"(c[3])
        : "r"(a[0]), "r"(a[1]), "r"(a[2]), "r"(a[3]), "r"(b0), "r"(b1));
}

// ---------------------------------------------------------------------------
// init: zero degrees; parallel index-dtype probe (warp ballot)
// ---------------------------------------------------------------------------
__global__ void k_init(const int* __restrict__ eiw) {
    int i = blockIdx.x * blockDim.x + threadIdx.x;
    if (i < NN) g_deg[i] = 0;
    if (blockIdx.x == 0 && threadIdx.x < 32) {
        int lane = threadIdx.x;
        int nz = (eiw[2 * lane + 1] != 0) | (eiw[2 * (lane + 32) + 1] != 0);
        unsigned bal = __ballot_sync(0xffffffffu, nz);
        if (lane == 0) { g_is64 = (bal == 0u); g_total = 0; }
    }
}

// ---------------------------------------------------------------------------
// Compact CSR build: hist -> alloc -> scatter
// ---------------------------------------------------------------------------
__global__ void k_hist(const void* __restrict__ ei) {
    int e = blockIdx.x * blockDim.x + threadIdx.x;
    if (e < EE) {
        int d = load_idx(ei, (long long)EE + e);
        if ((unsigned)d < NN) atomicAdd(&g_deg[d], 1);
    }
}

__global__ void k_alloc() {
    int i = blockIdx.x * blockDim.x + threadIdx.x;
    if (i < NN) {
        int dg = g_deg[i];
        int st = atomicAdd(&g_total, dg);
        g_start[i] = st;
        g_cur[i]   = st;
    }
}

__global__ void k_scatter(const void* __restrict__ ei) {
    int e = blockIdx.x * blockDim.x + threadIdx.x;
    if (e < EE) {
        int s = load_idx(ei, e);
        int d = load_idx(ei, (long long)EE + e);
        if ((unsigned)d < NN && (unsigned)s < NN) {
            int pos = atomicAdd(&g_cur[d], 1);
            g_csrc[pos] = s;
        }
    }
}

// ---------------------------------------------------------------------------
// 3xBF16 tensor-core GEMM: C[M,128] = A[M,128] @ B[128,128] (+bias)
// Block 128x128, 256 threads (8 warps, 2x4), warp tile 64x32, BK=16,
// double-buffered smem staging (R10).
// HALF_OUT: write fp16 into g_hpf (aggregation input); else fp32 into C.
// FUSE_ESED: epilogue computes es/ed row-dots (from exact fp32 accumulators).
// ---------------------------------------------------------------------------
#define PAD 136

template <bool FUSE_ESED, bool HALF_OUT>
__device__ __forceinline__ void mma_gemm_body(const float* __restrict__ A,
                                              const float* __restrict__ B,
                                              const float* __restrict__ bias,
                                              const float* __restrict__ asrc,
                                              const float* __restrict__ adst,
                                              float* __restrict__ C, int M) {
    __shared__ uint32_t Ah[2][8][PAD], Al[2][8][PAD];   // [buf][k-pair][m]
    __shared__ uint32_t Bh[2][8][PAD], Bl[2][8][PAD];   // [buf][k-pair][n]
    __shared__ float es_s[128], ed_s[128];

    const int tid  = threadIdx.x;
    const int warp = tid >> 5, lane = tid & 31;
    const int wm = warp >> 2, wn = warp & 3;
    const int gid = lane >> 2, tig = lane & 3;
    const int brow = blockIdx.x * 128;

    if (FUSE_ESED && tid < 128) { es_s[tid] = 0.f; ed_s[tid] = 0.f; }

    const int a_r  = tid & 63;
    const int a_kq = (tid >> 6) * 4;   // k offset within chunk (0 or 4)
    const int b_bp = tid >> 5;         // 0..7 (k-pair row)
    const int b_n  = (tid & 31) * 4;

    float acc[4][4][4];
    #pragma unroll
    for (int mt = 0; mt < 4; mt++)
        #pragma unroll
        for (int nt = 0; nt < 4; nt++)
            #pragma unroll
            for (int c = 0; c < 4; c++) acc[mt][nt][c] = 0.f;

    float4 av0, av1, bv0, bv1;   // prefetch registers

    auto load_chunk = [&](int kc) {
        int g0 = brow + a_r;
        int g1 = brow + a_r + 64;
        av0 = (g0 < M) ? *(const float4*)&A[(size_t)g0 * 128 + kc + a_kq]
                       : make_float4(0.f, 0.f, 0.f, 0.f);
        av1 = (g1 < M) ? *(const float4*)&A[(size_t)g1 * 128 + kc + a_kq]
                       : make_float4(0.f, 0.f, 0.f, 0.f);
        const float* B0 = &B[(size_t)(kc + 2 * b_bp) * 128 + b_n];
        bv0 = *(const float4*)B0;
        bv1 = *(const float4*)(B0 + 128);
    };

    auto store_chunk = [&](int buf) {
        #pragma unroll
        for (int p = 0; p < 2; p++) {
            float4 v = p ? av1 : av0;
            int r = a_r + 64 * p;
            float h0 = bf16_hi_val(v.x), h1 = bf16_hi_val(v.y);
            float h2 = bf16_hi_val(v.z), h3 = bf16_hi_val(v.w);
            Ah[buf][a_kq / 2][r]     = pack_bf16(v.x, v.y);
            Ah[buf][a_kq / 2 + 1][r] = pack_bf16(v.z, v.w);
            Al[buf][a_kq / 2][r]     = pack_bf16(v.x - h0, v.y - h1);
            Al[buf][a_kq / 2 + 1][r] = pack_bf16(v.z - h2, v.w - h3);
        }
        float f0[4] = {bv0.x, bv0.y, bv0.z, bv0.w};
        float f1[4] = {bv1.x, bv1.y, bv1.z, bv1.w};
        uint4 hq, lq;
        uint32_t* hp_ = (uint32_t*)&hq;
        uint32_t* lp_ = (uint32_t*)&lq;
        #pragma unroll
        for (int i = 0; i < 4; i++) {
            float h0 = bf16_hi_val(f0[i]), l0 = f0[i] - h0;
            float h1 = bf16_hi_val(f1[i]), l1 = f1[i] - h1;
            hp_[i] = pack_bf16(h0, h1);
            lp_[i] = pack_bf16(l0, l1);
        }
        *(uint4*)&Bh[buf][b_bp][b_n] = hq;
        *(uint4*)&Bl[buf][b_bp][b_n] = lq;
    };

    load_chunk(0);
    store_chunk(0);
    __syncthreads();

    #pragma unroll 1
    for (int c = 0; c < 8; c++) {
        const int cur = c & 1;
        if (c < 7) load_chunk((c + 1) * 16);

        {
            uint32_t ah[4][4], al[4][4];
            #pragma unroll
            for (int mt = 0; mt < 4; mt++) {
                int m0 = wm * 64 + mt * 16 + gid;
                ah[mt][0] = Ah[cur][tig][m0];     ah[mt][1] = Ah[cur][tig][m0 + 8];
                ah[mt][2] = Ah[cur][tig + 4][m0]; ah[mt][3] = Ah[cur][tig + 4][m0 + 8];
                al[mt][0] = Al[cur][tig][m0];     al[mt][1] = Al[cur][tig][m0 + 8];
                al[mt][2] = Al[cur][tig + 4][m0]; al[mt][3] = Al[cur][tig + 4][m0 + 8];
            }
            #pragma unroll
            for (int nt = 0; nt < 4; nt++) {
                int n0 = wn * 32 + nt * 8 + gid;
                uint32_t bh0 = Bh[cur][tig][n0], bh1 = Bh[cur][tig + 4][n0];
                uint32_t bl0 = Bl[cur][tig][n0], bl1 = Bl[cur][tig + 4][n0];
                #pragma unroll
                for (int mt = 0; mt < 4; mt++) {
                    mma_bf16(acc[mt][nt], ah[mt], bh0, bh1);
                    mma_bf16(acc[mt][nt], ah[mt], bl0, bl1);
                    mma_bf16(acc[mt][nt], al[mt], bh0, bh1);
                }
            }
        }

        if (c < 7) store_chunk(cur ^ 1);
        __syncthreads();
    }

    float as_v[4][2], ad_v[4][2];
    if (FUSE_ESED) {
        #pragma unroll
        for (int nt = 0; nt < 4; nt++) {
            int c0 = wn * 32 + nt * 8 + 2 * tig;
            as_v[nt][0] = asrc[c0]; as_v[nt][1] = asrc[c0 + 1];
            ad_v[nt][0] = adst[c0]; ad_v[nt][1] = adst[c0 + 1];
        }
    }

    #pragma unroll
    for (int mt = 0; mt < 4; mt++) {
        int r0 = brow + wm * 64 + mt * 16 + gid;
        float pe0 = 0.f, pe1 = 0.f, pd0 = 0.f, pd1 = 0.f;
        #pragma unroll
        for (int nt = 0; nt < 4; nt++) {
            int c0 = wn * 32 + nt * 8 + 2 * tig;
            float b0v = bias ? bias[c0]     : 0.f;
            float b1v = bias ? bias[c0 + 1] : 0.f;
            float v00 = acc[mt][nt][0] + b0v, v01 = acc[mt][nt][1] + b1v;
            float v10 = acc[mt][nt][2] + b0v, v11 = acc[mt][nt][3] + b1v;
            if (HALF_OUT) {
                if (r0 < M)     *(half2*)&g_hpf[(size_t)r0 * 128 + c0]       = __floats2half2_rn(v00, v01);
                if (r0 + 8 < M) *(half2*)&g_hpf[(size_t)(r0 + 8) * 128 + c0] = __floats2half2_rn(v10, v11);
            } else {
                if (r0 < M)     *(float2*)&C[(size_t)r0 * 128 + c0]       = make_float2(v00, v01);
                if (r0 + 8 < M) *(float2*)&C[(size_t)(r0 + 8) * 128 + c0] = make_float2(v10, v11);
            }
            if (FUSE_ESED) {
                pe0 += v00 * as_v[nt][0] + v01 * as_v[nt][1];
                pe1 += v10 * as_v[nt][0] + v11 * as_v[nt][1];
                pd0 += v00 * ad_v[nt][0] + v01 * ad_v[nt][1];
                pd1 += v10 * ad_v[nt][0] + v11 * ad_v[nt][1];
            }
        }
        if (FUSE_ESED) {
            #pragma unroll
            for (int o = 1; o <= 2; o <<= 1) {
                pe0 += __shfl_xor_sync(0xffffffffu, pe0, o);
                pe1 += __shfl_xor_sync(0xffffffffu, pe1, o);
                pd0 += __shfl_xor_sync(0xffffffffu, pd0, o);
                pd1 += __shfl_xor_sync(0xffffffffu, pd1, o);
            }
            if (tig == 0) {
                int lr = wm * 64 + mt * 16 + gid;
                atomicAdd(&es_s[lr], pe0);     atomicAdd(&es_s[lr + 8], pe1);
                atomicAdd(&ed_s[lr], pd0);     atomicAdd(&ed_s[lr + 8], pd1);
            }
        }
    }

    if (FUSE_ESED) {
        __syncthreads();
        if (tid < 128 && brow + tid < M) {
            g_es[brow + tid] = es_s[tid];
            g_ed[brow + tid] = ed_s[tid];
        }
    }
}

// mlp1: g_h = x @ W1 + b1 (fp32 out)
__global__ void __launch_bounds__(256, 2) k_mma_x(const float* __restrict__ A,
                                                  const float* __restrict__ B,
                                                  const float* __restrict__ bias) {
    mma_gemm_body<false, false>(A, B, bias, nullptr, nullptr, g_h, NN);
}

// per-layer: g_hpf = fp16(h @ Wg[l]), fused exact es/ed
__global__ void __launch_bounds__(256, 2) k_mma_h(const float* __restrict__ B,
                                                  const float* __restrict__ asrc,
                                                  const float* __restrict__ adst) {
    mma_gemm_body<true, true>(g_h, B, nullptr, asrc, adst, nullptr, NN);
}

// ---------------------------------------------------------------------------
// GAT aggregation (warp per destination node, compact CSR) — single pass,
// no max-shift softmax, fp16 gather, UNROLL x4: 4 edges' index loads, es
// loads, and feature gathers are batch-issued -> MLP 1 -> 4 in the bound path.
// ---------------------------------------------------------------------------
__global__ void k_gat_aggr(const float* __restrict__ bg) {
    int warp = (blockIdx.x * blockDim.x + threadIdx.x) >> 5;
    int lane = threadIdx.x & 31;
    if (warp >= NN) return;
    const int d = warp;
    const int lo = g_start[d], hi = lo + g_deg[d];
    const float ed_d = g_ed[d];
    const float e_self = leaky(g_es[d] + ed_d);

    // self-loop
    float ex_self = expf(e_self);
    float z = ex_self;
    uint2 sv = *(const uint2*)&g_hpf[(size_t)d * 128 + 4 * lane];
    float2 s0 = __half22float2(*(half2*)&sv.x);
    float2 s1 = __half22float2(*(half2*)&sv.y);
    float ax = ex_self * s0.x, ay = ex_self * s0.y;
    float az = ex_self * s1.x, aw = ex_self * s1.y;

    const size_t fo = 4 * lane;
    int j = lo;

    // 4-edge batches: issue all independent loads before any dependent math
    for (; j + 4 <= hi; j += 4) {
        int i0 = g_csrc[j],     i1 = g_csrc[j + 1];
        int i2 = g_csrc[j + 2], i3 = g_csrc[j + 3];
        float e0 = g_es[i0], e1 = g_es[i1], e2 = g_es[i2], e3 = g_es[i3];
        uint2 w0 = *(const uint2*)&g_hpf[(size_t)i0 * 128 + fo];
        uint2 w1 = *(const uint2*)&g_hpf[(size_t)i1 * 128 + fo];
        uint2 w2 = *(const uint2*)&g_hpf[(size_t)i2 * 128 + fo];
        uint2 w3 = *(const uint2*)&g_hpf[(size_t)i3 * 128 + fo];

        float x0 = expf(leaky(e0 + ed_d));
        float x1 = expf(leaky(e1 + ed_d));
        float x2 = expf(leaky(e2 + ed_d));
        float x3 = expf(leaky(e3 + ed_d));
        z += (x0 + x1) + (x2 + x3);

        float2 a0 = __half22float2(*(half2*)&w0.x), b0 = __half22float2(*(half2*)&w0.y);
        float2 a1 = __half22float2(*(half2*)&w1.x), b1 = __half22float2(*(half2*)&w1.y);
        float2 a2 = __half22float2(*(half2*)&w2.x), b2 = __half22float2(*(half2*)&w2.y);
        float2 a3 = __half22float2(*(half2*)&w3.x), b3 = __half22float2(*(half2*)&w3.y);

        ax = fmaf(x0, a0.x, ax); ay = fmaf(x0, a0.y, ay);
        az = fmaf(x0, b0.x, az); aw = fmaf(x0, b0.y, aw);
        ax = fmaf(x1, a1.x, ax); ay = fmaf(x1, a1.y, ay);
        az = fmaf(x1, b1.x, az); aw = fmaf(x1, b1.y, aw);
        ax = fmaf(x2, a2.x, ax); ay = fmaf(x2, a2.y, ay);
        az = fmaf(x2, b2.x, az); aw = fmaf(x2, b2.y, aw);
        ax = fmaf(x3, a3.x, ax); ay = fmaf(x3, a3.y, ay);
        az = fmaf(x3, b3.x, az); aw = fmaf(x3, b3.y, aw);
    }

    // remainder
    for (; j < hi; ++j) {
        int s = g_csrc[j];
        float ex = expf(leaky(g_es[s] + ed_d));
        z += ex;
        uint2 wv = *(const uint2*)&g_hpf[(size_t)s * 128 + fo];
        float2 w0 = __half22float2(*(half2*)&wv.x);
        float2 w1 = __half22float2(*(half2*)&wv.y);
        ax = fmaf(ex, w0.x, ax);
        ay = fmaf(ex, w0.y, ay);
        az = fmaf(ex, w1.x, az);
        aw = fmaf(ex, w1.y, aw);
    }
    const float invz = 1.0f / z;

    float4* h4 = (float4*)g_h;
    float4 b = ((const float4*)bg)[lane];
    float4 hin = h4[(size_t)d * 32 + lane];
    float4 o;
    o.x = fmaxf(fmaf(ax, invz, b.x), 0.f) + hin.x;
    o.y = fmaxf(fmaf(ay, invz, b.y), 0.f) + hin.y;
    o.z = fmaxf(fmaf(az, invz, b.z), 0.f) + hin.z;
    o.w = fmaxf(fmaf(aw, invz, b.w), 0.f) + hin.w;
    h4[(size_t)d * 32 + lane] = o;
}

// ---------------------------------------------------------------------------
// Fused pool + final projection: block per graph (batch sorted)
// ---------------------------------------------------------------------------
__global__ void k_poolfinal(const void* __restrict__ batch,
                            const float* __restrict__ W2,
                            const float* __restrict__ b2,
                            float* __restrict__ out) {
    __shared__ float ps[128];
    __shared__ int s_lo, s_hi;
    const int g = blockIdx.x;
    const int tid = threadIdx.x;
    if (tid == 0) {
        int lo = 0, hi = NN;
        while (lo < hi) { int mid = (lo + hi) >> 1; if (load_idx(batch, mid) < g) lo = mid + 1; else hi = mid; }
        s_lo = lo;
        lo = 0; hi = NN;
        int g1 = g + 1;
        while (lo < hi) { int mid = (lo + hi) >> 1; if (load_idx(batch, mid) < g1) lo = mid + 1; else hi = mid; }
        s_hi = lo;
    }
    __syncthreads();
    float acc = 0.f;
    for (int i = s_lo; i < s_hi; ++i) acc += g_h[(size_t)i * 128 + tid];
    ps[tid] = acc;
    __syncthreads();
    if (tid < 64) {
        float o = b2[tid];
        #pragma unroll 8
        for (int k = 0; k < 128; ++k)
            o = fmaf(ps[k], W2[k * 64 + tid], o);
        out[g * 64 + tid] = o;
    }
}

// ---------------------------------------------------------------------------
// Launch
// ---------------------------------------------------------------------------
extern "C" void kernel_launch(void* const* d_in, const int* in_sizes, int n_in,
                              void* d_out, int out_size) {
    const float* x     = (const float*)d_in[0];
    const void*  ei    = d_in[1];
    const void*  batch = d_in[2];
    const float* W1    = (const float*)d_in[3];
    const float* b1    = (const float*)d_in[4];
    const float* Wg    = (const float*)d_in[5];
    const float* asrc  = (const float*)d_in[6];
    const float* adst  = (const float*)d_in[7];
    const float* bg    = (const float*)d_in[8];
    const float* W2    = (const float*)d_in[9];
    const float* b2    = (const float*)d_in[10];
    float*       out   = (float*)d_out;

    k_init<<<(NN + 255) / 256, 256>>>((const int*)ei);
    k_hist<<<(EE + 255) / 256, 256>>>(ei);
    k_alloc<<<(NN + 255) / 256, 256>>>();
    k_scatter<<<(EE + 255) / 256, 256>>>(ei);

    const int gemm_blocks = (NN + 127) / 128;
    const int node_warp_blocks = (NN * 32 + 255) / 256;

    k_mma_x<<<gemm_blocks, 256>>>(x, W1, b1);

    for (int l = 0; l < NLAYERS; ++l) {
        k_mma_h<<<gemm_blocks, 256>>>(Wg + (size_t)l * 128 * 128,
                                      asrc + l * 128, adst + l * 128);
        k_gat_aggr<<<node_warp_blocks, 256>>>(bg + l * 128);
    }

    k_poolfinal<<<NG, 128>>>(batch, W2, b2, out);
}

// round 13
// speedup vs baseline: 1.3239x; 1.0016x over previous
#include <cuda_runtime.h>
#include <cuda_bf16.h>
#include <cuda_fp16.h>
#include <math.h>
#include <stdint.h>

// Problem constants (match reference)
#define NN      50000
#define EE      600000
#define D_IN    128
#define D_H     128
#define D_OUT   64
#define NLAYERS 3
#define NG      64
#define SLOPE   0.2f

// ---------------------------------------------------------------------------
// Device scratch (g_deg/g_total statically zeroed; re-zeroed by k_poolfinal)
// ---------------------------------------------------------------------------
__device__ __align__(16) float  g_h  [NN * D_H];   // fp32 features (residual/pool)
__device__ __align__(16) __half g_hpf[NN * D_H];   // fp16 h@W (aggregation gathers)
__device__ float g_es[NN];
__device__ float g_ed[NN];
__device__ int   g_deg[NN];
__device__ int   g_start[NN];
__device__ int   g_cur[NN];
__device__ int   g_total;
__device__ int   g_csrc[EE];                       // compact CSR-by-dst source ids

__device__ __forceinline__ float leaky(float x) {
    return x >= 0.f ? x : SLOPE * x;
}

__device__ __forceinline__ int load_idx2(const void* p, long long i, int is64) {
    return is64 ? (int)((const long long*)p)[i] : ((const int*)p)[i];
}

// Per-block index-dtype probe: int64 node ids (<50000) have all odd 32-bit
// words zero; int32 ids are random (first odd word nonzero w.h.p.).
// One warp, ballot, result in *flag (shared). Callers __syncthreads() after.
__device__ __forceinline__ void probe_is64(const void* ei, int* flag) {
    if (threadIdx.x < 32) {
        const int* w = (const int*)ei;
        int lane = threadIdx.x;
        int nz = (w[2 * lane + 1] != 0) | (w[2 * (lane + 32) + 1] != 0);
        unsigned bal = __ballot_sync(0xffffffffu, nz);
        if (lane == 0) *flag = (bal == 0u);
    }
}

// pack two floats as bf16x2: low half = a (even k), high half = b (odd k)
__device__ __forceinline__ uint32_t pack_bf16(float a, float b) {
    uint32_t r;
    asm("cvt.rn.bf16x2.f32 %0, %1, %2;" : "=r"(r) : "f"(b), "f"(a));
    return r;
}

__device__ __forceinline__ float bf16_hi_val(float x) {
    __nv_bfloat16 h = __float2bfloat16_rn(x);
    return __bfloat162float(h);
}

__device__ __forceinline__ void mma_bf16(float c[4], const uint32_t a[4],
                                         uint32_t b0, uint32_t b1) {
    asm volatile(
        "mma.sync.aligned.m16n8k16.row.col.f32.bf16.bf16.f32 "
        "{%0,%1,%2,%3}, {%4,%5,%6,%7}, {%8,%9}, {%0,%1,%2,%3};\n"
        : "+f"(c[0]), "+f"(c[1]), "+f"(c[2]), "+f"(c[3])
        : "r"(a[0]), "r"(a[1]), "r"(a[2]), "r"(a[3]), "r"(b0), "r"(b1));
}

// ---------------------------------------------------------------------------
// Compact CSR build: hist -> alloc -> scatter (g_deg pre-zeroed)
// ---------------------------------------------------------------------------
__global__ void k_hist(const void* __restrict__ ei) {
    __shared__ int s64;
    probe_is64(ei, &s64);
    __syncthreads();
    int e = blockIdx.x * blockDim.x + threadIdx.x;
    if (e < EE) {
        int d = load_idx2(ei, (long long)EE + e, s64);
        if ((unsigned)d < NN) atomicAdd(&g_deg[d], 1);
    }
}

__global__ void k_alloc() {
    int i = blockIdx.x * blockDim.x + threadIdx.x;
    if (i < NN) {
        int dg = g_deg[i];
        int st = atomicAdd(&g_total, dg);
        g_start[i] = st;
        g_cur[i]   = st;
    }
}

__global__ void k_scatter(const void* __restrict__ ei) {
    __shared__ int s64;
    probe_is64(ei, &s64);
    __syncthreads();
    int e = blockIdx.x * blockDim.x + threadIdx.x;
    if (e < EE) {
        int s = load_idx2(ei, e, s64);
        int d = load_idx2(ei, (long long)EE + e, s64);
        if ((unsigned)d < NN && (unsigned)s < NN) {
            int pos = atomicAdd(&g_cur[d], 1);
            g_csrc[pos] = s;
        }
    }
}

// ---------------------------------------------------------------------------
// 3xBF16 tensor-core GEMM: C[M,128] = A[M,128] @ B[128,128] (+bias)
// Block 64x128, 256 threads (8 warps, 2x4), warp tile 32x32, BK=16,
// double-buffered smem staging. Smaller tile: acc 32 regs -> 3 blocks/SM,
// 782 blocks -> cheaper tail wave.
// HALF_OUT: write fp16 into g_hpf; else fp32 into C.
// FUSE_ESED: epilogue computes es/ed row-dots from fp32 accumulators.
// ---------------------------------------------------------------------------
#define PAD_A 72
#define PAD_B 136

template <bool FUSE_ESED, bool HALF_OUT>
__device__ __forceinline__ void mma_gemm_body(const float* __restrict__ A,
                                              const float* __restrict__ B,
                                              const float* __restrict__ bias,
                                              const float* __restrict__ asrc,
                                              const float* __restrict__ adst,
                                              float* __restrict__ C, int M) {
    __shared__ uint32_t Ah[2][8][PAD_A], Al[2][8][PAD_A];   // [buf][k-pair][m]
    __shared__ uint32_t Bh[2][8][PAD_B], Bl[2][8][PAD_B];   // [buf][k-pair][n]
    __shared__ float es_s[64], ed_s[64];

    const int tid  = threadIdx.x;
    const int warp = tid >> 5, lane = tid & 31;
    const int wm = warp >> 2, wn = warp & 3;   // 2 x 4 warp grid
    const int gid = lane >> 2, tig = lane & 3;
    const int brow = blockIdx.x * 64;

    if (FUSE_ESED && tid < 64) { es_s[tid] = 0.f; ed_s[tid] = 0.f; }

    const int a_r  = tid & 63;
    const int a_kq = (tid >> 6) * 4;   // k offset within chunk: 0,4,8,12
    const int b_bp = tid >> 5;         // 0..7 (k-pair row)
    const int b_n  = (tid & 31) * 4;

    float acc[2][4][4];
    #pragma unroll
    for (int mt = 0; mt < 2; mt++)
        #pragma unroll
        for (int nt = 0; nt < 4; nt++)
            #pragma unroll
            for (int c = 0; c < 4; c++) acc[mt][nt][c] = 0.f;

    float4 av, bv0, bv1;   // prefetch registers

    auto load_chunk = [&](int kc) {
        int g0 = brow + a_r;
        av = (g0 < M) ? *(const float4*)&A[(size_t)g0 * 128 + kc + a_kq]
                      : make_float4(0.f, 0.f, 0.f, 0.f);
        const float* B0 = &B[(size_t)(kc + 2 * b_bp) * 128 + b_n];
        bv0 = *(const float4*)B0;
        bv1 = *(const float4*)(B0 + 128);
    };

    auto store_chunk = [&](int buf) {
        {
            float h0 = bf16_hi_val(av.x), h1 = bf16_hi_val(av.y);
            float h2 = bf16_hi_val(av.z), h3 = bf16_hi_val(av.w);
            Ah[buf][a_kq / 2][a_r]     = pack_bf16(av.x, av.y);
            Ah[buf][a_kq / 2 + 1][a_r] = pack_bf16(av.z, av.w);
            Al[buf][a_kq / 2][a_r]     = pack_bf16(av.x - h0, av.y - h1);
            Al[buf][a_kq / 2 + 1][a_r] = pack_bf16(av.z - h2, av.w - h3);
        }
        float f0[4] = {bv0.x, bv0.y, bv0.z, bv0.w};
        float f1[4] = {bv1.x, bv1.y, bv1.z, bv1.w};
        uint4 hq, lq;
        uint32_t* hp_ = (uint32_t*)&hq;
        uint32_t* lp_ = (uint32_t*)&lq;
        #pragma unroll
        for (int i = 0; i < 4; i++) {
            float h0 = bf16_hi_val(f0[i]), l0 = f0[i] - h0;
            float h1 = bf16_hi_val(f1[i]), l1 = f1[i] - h1;
            hp_[i] = pack_bf16(h0, h1);
            lp_[i] = pack_bf16(l0, l1);
        }
        *(uint4*)&Bh[buf][b_bp][b_n] = hq;
        *(uint4*)&Bl[buf][b_bp][b_n] = lq;
    };

    load_chunk(0);
    store_chunk(0);
    __syncthreads();

    #pragma unroll 1
    for (int c = 0; c < 8; c++) {
        const int cur = c & 1;
        if (c < 7) load_chunk((c + 1) * 16);

        {
            uint32_t ah[2][4], al[2][4];
            #pragma unroll
            for (int mt = 0; mt < 2; mt++) {
                int m0 = wm * 32 + mt * 16 + gid;
                ah[mt][0] = Ah[cur][tig][m0];     ah[mt][1] = Ah[cur][tig][m0 + 8];
                ah[mt][2] = Ah[cur][tig + 4][m0]; ah[mt][3] = Ah[cur][tig + 4][m0 + 8];
                al[mt][0] = Al[cur][tig][m0];     al[mt][1] = Al[cur][tig][m0 + 8];
                al[mt][2] = Al[cur][tig + 4][m0]; al[mt][3] = Al[cur][tig + 4][m0 + 8];
            }
            #pragma unroll
            for (int nt = 0; nt < 4; nt++) {
                int n0 = wn * 32 + nt * 8 + gid;
                uint32_t bh0 = Bh[cur][tig][n0], bh1 = Bh[cur][tig + 4][n0];
                uint32_t bl0 = Bl[cur][tig][n0], bl1 = Bl[cur][tig + 4][n0];
                #pragma unroll
                for (int mt = 0; mt < 2; mt++) {
                    mma_bf16(acc[mt][nt], ah[mt], bh0, bh1);
                    mma_bf16(acc[mt][nt], ah[mt], bl0, bl1);
                    mma_bf16(acc[mt][nt], al[mt], bh0, bh1);
                }
            }
        }

        if (c < 7) store_chunk(cur ^ 1);
        __syncthreads();
    }

    float as_v[4][2], ad_v[4][2];
    if (FUSE_ESED) {
        #pragma unroll
        for (int nt = 0; nt < 4; nt++) {
            int c0 = wn * 32 + nt * 8 + 2 * tig;
            as_v[nt][0] = asrc[c0]; as_v[nt][1] = asrc[c0 + 1];
            ad_v[nt][0] = adst[c0]; ad_v[nt][1] = adst[c0 + 1];
        }
    }

    #pragma unroll
    for (int mt = 0; mt < 2; mt++) {
        int r0 = brow + wm * 32 + mt * 16 + gid;
        float pe0 = 0.f, pe1 = 0.f, pd0 = 0.f, pd1 = 0.f;
        #pragma unroll
        for (int nt = 0; nt < 4; nt++) {
            int c0 = wn * 32 + nt * 8 + 2 * tig;
            float b0v = bias ? bias[c0]     : 0.f;
            float b1v = bias ? bias[c0 + 1] : 0.f;
            float v00 = acc[mt][nt][0] + b0v, v01 = acc[mt][nt][1] + b1v;
            float v10 = acc[mt][nt][2] + b0v, v11 = acc[mt][nt][3] + b1v;
            if (HALF_OUT) {
                if (r0 < M)     *(half2*)&g_hpf[(size_t)r0 * 128 + c0]       = __floats2half2_rn(v00, v01);
                if (r0 + 8 < M) *(half2*)&g_hpf[(size_t)(r0 + 8) * 128 + c0] = __floats2half2_rn(v10, v11);
            } else {
                if (r0 < M)     *(float2*)&C[(size_t)r0 * 128 + c0]       = make_float2(v00, v01);
                if (r0 + 8 < M) *(float2*)&C[(size_t)(r0 + 8) * 128 + c0] = make_float2(v10, v11);
            }
            if (FUSE_ESED) {
                pe0 += v00 * as_v[nt][0] + v01 * as_v[nt][1];
                pe1 += v10 * as_v[nt][0] + v11 * as_v[nt][1];
                pd0 += v00 * ad_v[nt][0] + v01 * ad_v[nt][1];
                pd1 += v10 * ad_v[nt][0] + v11 * ad_v[nt][1];
            }
        }
        if (FUSE_ESED) {
            #pragma unroll
            for (int o = 1; o <= 2; o <<= 1) {
                pe0 += __shfl_xor_sync(0xffffffffu, pe0, o);
                pe1 += __shfl_xor_sync(0xffffffffu, pe1, o);
                pd0 += __shfl_xor_sync(0xffffffffu, pd0, o);
                pd1 += __shfl_xor_sync(0xffffffffu, pd1, o);
            }
            if (tig == 0) {
                int lr = wm * 32 + mt * 16 + gid;
                atomicAdd(&es_s[lr], pe0);     atomicAdd(&es_s[lr + 8], pe1);
                atomicAdd(&ed_s[lr], pd0);     atomicAdd(&ed_s[lr + 8], pd1);
            }
        }
    }

    if (FUSE_ESED) {
        __syncthreads();
        if (tid < 64 && brow + tid < M) {
            g_es[brow + tid] = es_s[tid];
            g_ed[brow + tid] = ed_s[tid];
        }
    }
}

// mlp1: g_h = x @ W1 + b1 (fp32 out)
__global__ void __launch_bounds__(256, 3) k_mma_x(const float* __restrict__ A,
                                                  const float* __restrict__ B,
                                                  const float* __restrict__ bias) {
    mma_gemm_body<false, false>(A, B, bias, nullptr, nullptr, g_h, NN);
}

// per-layer: g_hpf = fp16(h @ Wg[l]), fused exact es/ed
__global__ void __launch_bounds__(256, 3) k_mma_h(const float* __restrict__ B,
                                                  const float* __restrict__ asrc,
                                                  const float* __restrict__ adst) {
    mma_gemm_body<true, true>(g_h, B, nullptr, asrc, adst, nullptr, NN);
}

// ---------------------------------------------------------------------------
// GAT aggregation (warp per destination node, compact CSR) — single pass,
// no max-shift softmax, fp16 gather, x4 batched loads.
// ---------------------------------------------------------------------------
__global__ void k_gat_aggr(const float* __restrict__ bg) {
    int warp = (blockIdx.x * blockDim.x + threadIdx.x) >> 5;
    int lane = threadIdx.x & 31;
    if (warp >= NN) return;
    const int d = warp;
    const int lo = g_start[d], hi = lo + g_deg[d];
    const float ed_d = g_ed[d];
    const float e_self = leaky(g_es[d] + ed_d);

    float ex_self = expf(e_self);
    float z = ex_self;
    uint2 sv = *(const uint2*)&g_hpf[(size_t)d * 128 + 4 * lane];
    float2 s0 = __half22float2(*(half2*)&sv.x);
    float2 s1 = __half22float2(*(half2*)&sv.y);
    float ax = ex_self * s0.x, ay = ex_self * s0.y;
    float az = ex_self * s1.x, aw = ex_self * s1.y;

    const size_t fo = 4 * lane;
    int j = lo;

    for (; j + 4 <= hi; j += 4) {
        int i0 = g_csrc[j],     i1 = g_csrc[j + 1];
        int i2 = g_csrc[j + 2], i3 = g_csrc[j + 3];
        float e0 = g_es[i0], e1 = g_es[i1], e2 = g_es[i2], e3 = g_es[i3];
        uint2 w0 = *(const uint2*)&g_hpf[(size_t)i0 * 128 + fo];
        uint2 w1 = *(const uint2*)&g_hpf[(size_t)i1 * 128 + fo];
        uint2 w2 = *(const uint2*)&g_hpf[(size_t)i2 * 128 + fo];
        uint2 w3 = *(const uint2*)&g_hpf[(size_t)i3 * 128 + fo];

        float x0 = expf(leaky(e0 + ed_d));
        float x1 = expf(leaky(e1 + ed_d));
        float x2 = expf(leaky(e2 + ed_d));
        float x3 = expf(leaky(e3 + ed_d));
        z += (x0 + x1) + (x2 + x3);

        float2 a0 = __half22float2(*(half2*)&w0.x), b0 = __half22float2(*(half2*)&w0.y);
        float2 a1 = __half22float2(*(half2*)&w1.x), b1 = __half22float2(*(half2*)&w1.y);
        float2 a2 = __half22float2(*(half2*)&w2.x), b2 = __half22float2(*(half2*)&w2.y);
        float2 a3 = __half22float2(*(half2*)&w3.x), b3 = __half22float2(*(half2*)&w3.y);

        ax = fmaf(x0, a0.x, ax); ay = fmaf(x0, a0.y, ay);
        az = fmaf(x0, b0.x, az); aw = fmaf(x0, b0.y, aw);
        ax = fmaf(x1, a1.x, ax); ay = fmaf(x1, a1.y, ay);
        az = fmaf(x1, b1.x, az); aw = fmaf(x1, b1.y, aw);
        ax = fmaf(x2, a2.x, ax); ay = fmaf(x2, a2.y, ay);
        az = fmaf(x2, b2.x, az); aw = fmaf(x2, b2.y, aw);
        ax = fmaf(x3, a3.x, ax); ay = fmaf(x3, a3.y, ay);
        az = fmaf(x3, b3.x, az); aw = fmaf(x3, b3.y, aw);
    }

    for (; j < hi; ++j) {
        int s = g_csrc[j];
        float ex = expf(leaky(g_es[s] + ed_d));
        z += ex;
        uint2 wv = *(const uint2*)&g_hpf[(size_t)s * 128 + fo];
        float2 w0 = __half22float2(*(half2*)&wv.x);
        float2 w1 = __half22float2(*(half2*)&wv.y);
        ax = fmaf(ex, w0.x, ax);
        ay = fmaf(ex, w0.y, ay);
        az = fmaf(ex, w1.x, az);
        aw = fmaf(ex, w1.y, aw);
    }
    const float invz = 1.0f / z;

    float4* h4 = (float4*)g_h;
    float4 b = ((const float4*)bg)[lane];
    float4 hin = h4[(size_t)d * 32 + lane];
    float4 o;
    o.x = fmaxf(fmaf(ax, invz, b.x), 0.f) + hin.x;
    o.y = fmaxf(fmaf(ay, invz, b.y), 0.f) + hin.y;
    o.z = fmaxf(fmaf(az, invz, b.z), 0.f) + hin.z;
    o.w = fmaxf(fmaf(aw, invz, b.w), 0.f) + hin.w;
    h4[(size_t)d * 32 + lane] = o;
}

// ---------------------------------------------------------------------------
// Fused pool + final projection; also re-zeroes g_deg/g_total for the next
// run (deterministic: every call sees zeroed counters, leaves them zeroed).
// ---------------------------------------------------------------------------
__global__ void k_poolfinal(const void* __restrict__ ei,
                            const void* __restrict__ batch,
                            const float* __restrict__ W2,
                            const float* __restrict__ b2,
                            float* __restrict__ out) {
    __shared__ float ps[128];
    __shared__ int s_lo, s_hi, s64;
    const int g = blockIdx.x;
    const int tid = threadIdx.x;
    probe_is64(ei, &s64);
    __syncthreads();
    if (tid == 0) {
        int lo = 0, hi = NN;
        while (lo < hi) { int mid = (lo + hi) >> 1; if (load_idx2(batch, mid, s64) < g) lo = mid + 1; else hi = mid; }
        s_lo = lo;
        lo = 0; hi = NN;
        int g1 = g + 1;
        while (lo < hi) { int mid = (lo + hi) >> 1; if (load_idx2(batch, mid, s64) < g1) lo = mid + 1; else hi = mid; }
        s_hi = lo;
    }
    __syncthreads();
    float acc = 0.f;
    for (int i = s_lo; i < s_hi; ++i) acc += g_h[(size_t)i * 128 + tid];
    ps[tid] = acc;
    __syncthreads();
    if (tid < 64) {
        float o = b2[tid];
        #pragma unroll 8
        for (int k = 0; k < 128; ++k)
            o = fmaf(ps[k], W2[k * 64 + tid], o);
        out[g * 64 + tid] = o;
    }
    // reset CSR counters for the next invocation
    for (int i = g * 128 + tid; i < NN; i += NG * 128) g_deg[i] = 0;
    if (g == 0 && tid == 0) g_total = 0;
}

// ---------------------------------------------------------------------------
// Launch (11 kernels)
// ---------------------------------------------------------------------------
extern "C" void kernel_launch(void* const* d_in, const int* in_sizes, int n_in,
                              void* d_out, int out_size) {
    const float* x     = (const float*)d_in[0];
    const void*  ei    = d_in[1];
    const void*  batch = d_in[2];
    const float* W1    = (const float*)d_in[3];
    const float* b1    = (const float*)d_in[4];
    const float* Wg    = (const float*)d_in[5];
    const float* asrc  = (const float*)d_in[6];
    const float* adst  = (const float*)d_in[7];
    const float* bg    = (const float*)d_in[8];
    const float* W2    = (const float*)d_in[9];
    const float* b2    = (const float*)d_in[10];
    float*       out   = (float*)d_out;

    k_hist<<<(EE + 255) / 256, 256>>>(ei);
    k_alloc<<<(NN + 255) / 256, 256>>>();
    k_scatter<<<(EE + 255) / 256, 256>>>(ei);

    const int gemm_blocks = (NN + 63) / 64;
    const int node_warp_blocks = (NN * 32 + 255) / 256;

    k_mma_x<<<gemm_blocks, 256>>>(x, W1, b1);

    for (int l = 0; l < NLAYERS; ++l) {
        k_mma_h<<<gemm_blocks, 256>>>(Wg + (size_t)l * 128 * 128,
                                      asrc + l * 128, adst + l * 128);
        k_gat_aggr<<<node_warp_blocks, 256>>>(bg + l * 128);
    }

    k_poolfinal<<<NG, 128>>>(ei, batch, W2, b2, out);
}

// round 14
// speedup vs baseline: 1.4693x; 1.1098x over previous
#include <cuda_runtime.h>
#include <cuda_bf16.h>
#include <cuda_fp16.h>
#include <math.h>
#include <stdint.h>

// Problem constants (match reference)
#define NN      50000
#define EE      600000
#define D_IN    128
#define D_H     128
#define D_OUT   64
#define NLAYERS 3
#define NG      64
#define SLOPE   0.2f

// ---------------------------------------------------------------------------
// Device scratch (g_deg/g_total statically zeroed; re-zeroed by k_poolfinal)
// ---------------------------------------------------------------------------
__device__ __align__(16) float  g_h  [NN * D_H];   // fp32 features (residual/pool)
__device__ __align__(16) __half g_hpf[NN * D_H];   // fp16 h@W (aggregation gathers)
__device__ float g_es[NN];
__device__ float g_ed[NN];
__device__ int   g_deg[NN];
__device__ int   g_start[NN];
__device__ int   g_cur[NN];
__device__ int   g_total;
__device__ int   g_csrc[EE];                       // compact CSR-by-dst source ids

__device__ __forceinline__ float leaky(float x) {
    return x >= 0.f ? x : SLOPE * x;
}

__device__ __forceinline__ int load_idx2(const void* p, long long i, int is64) {
    return is64 ? (int)((const long long*)p)[i] : ((const int*)p)[i];
}

// Per-block index-dtype probe (warp ballot into shared flag)
__device__ __forceinline__ void probe_is64(const void* ei, int* flag) {
    if (threadIdx.x < 32) {
        const int* w = (const int*)ei;
        int lane = threadIdx.x;
        int nz = (w[2 * lane + 1] != 0) | (w[2 * (lane + 32) + 1] != 0);
        unsigned bal = __ballot_sync(0xffffffffu, nz);
        if (lane == 0) *flag = (bal == 0u);
    }
}

// pack two floats as f16x2 (one cvt instruction)
__device__ __forceinline__ uint32_t pack_f16(float a, float b) {
    half2 h = __floats2half2_rn(a, b);
    return *(uint32_t*)&h;
}

// m16n8k16 fp16 MMA, fp32 accumulate
__device__ __forceinline__ void mma_f16(float c[4], const uint32_t a[4],
                                        uint32_t b0, uint32_t b1) {
    asm volatile(
        "mma.sync.aligned.m16n8k16.row.col.f32.f16.f16.f32 "
        "{%0,%1,%2,%3}, {%4,%5,%6,%7}, {%8,%9}, {%0,%1,%2,%3};\n"
        : "+f"(c[0]), "+f"(c[1]), "+f"(c[2]), "+f"(c[3])
        : "r"(a[0]), "r"(a[1]), "r"(a[2]), "r"(a[3]), "r"(b0), "r"(b1));
}

// ---------------------------------------------------------------------------
// Compact CSR build: hist -> alloc -> scatter (g_deg pre-zeroed)
// ---------------------------------------------------------------------------
__global__ void k_hist(const void* __restrict__ ei) {
    __shared__ int s64;
    probe_is64(ei, &s64);
    __syncthreads();
    int e = blockIdx.x * blockDim.x + threadIdx.x;
    if (e < EE) {
        int d = load_idx2(ei, (long long)EE + e, s64);
        if ((unsigned)d < NN) atomicAdd(&g_deg[d], 1);
    }
}

__global__ void k_alloc() {
    int i = blockIdx.x * blockDim.x + threadIdx.x;
    if (i < NN) {
        int dg = g_deg[i];
        int st = atomicAdd(&g_total, dg);
        g_start[i] = st;
        g_cur[i]   = st;
    }
}

__global__ void k_scatter(const void* __restrict__ ei) {
    __shared__ int s64;
    probe_is64(ei, &s64);
    __syncthreads();
    int e = blockIdx.x * blockDim.x + threadIdx.x;
    if (e < EE) {
        int s = load_idx2(ei, e, s64);
        int d = load_idx2(ei, (long long)EE + e, s64);
        if ((unsigned)d < NN && (unsigned)s < NN) {
            int pos = atomicAdd(&g_cur[d], 1);
            g_csrc[pos] = s;
        }
    }
}

// ---------------------------------------------------------------------------
// fp16 tensor-core GEMM: C[M,128] = A[M,128] @ B[128,128] (+bias)
// Block 64x128, 256 threads (8 warps, 2x4), warp tile 32x32, BK=16,
// double-buffered smem staging. SINGLE fp16 MMA per fragment (no hi/lo):
// 1/3 the MMA issues, 1/2 the fragment LDS traffic, 1/3 the cvt chain.
// HALF_OUT: write fp16 into g_hpf; else fp32 into C.
// FUSE_ESED: epilogue computes es/ed row-dots from fp32 accumulators.
// ---------------------------------------------------------------------------
#define PAD_A 72
#define PAD_B 136

template <bool FUSE_ESED, bool HALF_OUT>
__device__ __forceinline__ void mma_gemm_body(const float* __restrict__ A,
                                              const float* __restrict__ B,
                                              const float* __restrict__ bias,
                                              const float* __restrict__ asrc,
                                              const float* __restrict__ adst,
                                              float* __restrict__ C, int M) {
    __shared__ uint32_t Ah[2][8][PAD_A];   // [buf][k-pair][m]
    __shared__ uint32_t Bh[2][8][PAD_B];   // [buf][k-pair][n]
    __shared__ float es_s[64], ed_s[64];

    const int tid  = threadIdx.x;
    const int warp = tid >> 5, lane = tid & 31;
    const int wm = warp >> 2, wn = warp & 3;   // 2 x 4 warp grid
    const int gid = lane >> 2, tig = lane & 3;
    const int brow = blockIdx.x * 64;

    if (FUSE_ESED && tid < 64) { es_s[tid] = 0.f; ed_s[tid] = 0.f; }

    const int a_r  = tid & 63;
    const int a_kq = (tid >> 6) * 4;   // k offset within chunk: 0 or 4 (x2 halves)
    const int b_bp = tid >> 5;         // 0..7 (k-pair row)
    const int b_n  = (tid & 31) * 4;

    float acc[2][4][4];
    #pragma unroll
    for (int mt = 0; mt < 2; mt++)
        #pragma unroll
        for (int nt = 0; nt < 4; nt++)
            #pragma unroll
            for (int c = 0; c < 4; c++) acc[mt][nt][c] = 0.f;

    float4 av, bv0, bv1;   // prefetch registers

    auto load_chunk = [&](int kc) {
        int g0 = brow + a_r;
        av = (g0 < M) ? *(const float4*)&A[(size_t)g0 * 128 + kc + a_kq]
                      : make_float4(0.f, 0.f, 0.f, 0.f);
        const float* B0 = &B[(size_t)(kc + 2 * b_bp) * 128 + b_n];
        bv0 = *(const float4*)B0;
        bv1 = *(const float4*)(B0 + 128);
    };

    auto store_chunk = [&](int buf) {
        Ah[buf][a_kq / 2][a_r]     = pack_f16(av.x, av.y);
        Ah[buf][a_kq / 2 + 1][a_r] = pack_f16(av.z, av.w);
        uint4 hq;
        uint32_t* hp_ = (uint32_t*)&hq;
        hp_[0] = pack_f16(bv0.x, bv1.x);
        hp_[1] = pack_f16(bv0.y, bv1.y);
        hp_[2] = pack_f16(bv0.z, bv1.z);
        hp_[3] = pack_f16(bv0.w, bv1.w);
        *(uint4*)&Bh[buf][b_bp][b_n] = hq;
    };

    load_chunk(0);
    store_chunk(0);
    __syncthreads();

    #pragma unroll 1
    for (int c = 0; c < 8; c++) {
        const int cur = c & 1;
        if (c < 7) load_chunk((c + 1) * 16);

        {
            uint32_t ah[2][4];
            #pragma unroll
            for (int mt = 0; mt < 2; mt++) {
                int m0 = wm * 32 + mt * 16 + gid;
                ah[mt][0] = Ah[cur][tig][m0];     ah[mt][1] = Ah[cur][tig][m0 + 8];
                ah[mt][2] = Ah[cur][tig + 4][m0]; ah[mt][3] = Ah[cur][tig + 4][m0 + 8];
            }
            #pragma unroll
            for (int nt = 0; nt < 4; nt++) {
                int n0 = wn * 32 + nt * 8 + gid;
                uint32_t bh0 = Bh[cur][tig][n0], bh1 = Bh[cur][tig + 4][n0];
                #pragma unroll
                for (int mt = 0; mt < 2; mt++)
                    mma_f16(acc[mt][nt], ah[mt], bh0, bh1);
            }
        }

        if (c < 7) store_chunk(cur ^ 1);
        __syncthreads();
    }

    float as_v[4][2], ad_v[4][2];
    if (FUSE_ESED) {
        #pragma unroll
        for (int nt = 0; nt < 4; nt++) {
            int c0 = wn * 32 + nt * 8 + 2 * tig;
            as_v[nt][0] = asrc[c0]; as_v[nt][1] = asrc[c0 + 1];
            ad_v[nt][0] = adst[c0]; ad_v[nt][1] = adst[c0 + 1];
        }
    }

    #pragma unroll
    for (int mt = 0; mt < 2; mt++) {
        int r0 = brow + wm * 32 + mt * 16 + gid;
        float pe0 = 0.f, pe1 = 0.f, pd0 = 0.f, pd1 = 0.f;
        #pragma unroll
        for (int nt = 0; nt < 4; nt++) {
            int c0 = wn * 32 + nt * 8 + 2 * tig;
            float b0v = bias ? bias[c0]     : 0.f;
            float b1v = bias ? bias[c0 + 1] : 0.f;
            float v00 = acc[mt][nt][0] + b0v, v01 = acc[mt][nt][1] + b1v;
            float v10 = acc[mt][nt][2] + b0v, v11 = acc[mt][nt][3] + b1v;
            if (HALF_OUT) {
                if (r0 < M)     *(half2*)&g_hpf[(size_t)r0 * 128 + c0]       = __floats2half2_rn(v00, v01);
                if (r0 + 8 < M) *(half2*)&g_hpf[(size_t)(r0 + 8) * 128 + c0] = __floats2half2_rn(v10, v11);
            } else {
                if (r0 < M)     *(float2*)&C[(size_t)r0 * 128 + c0]       = make_float2(v00, v01);
                if (r0 + 8 < M) *(float2*)&C[(size_t)(r0 + 8) * 128 + c0] = make_float2(v10, v11);
            }
            if (FUSE_ESED) {
                pe0 += v00 * as_v[nt][0] + v01 * as_v[nt][1];
                pe1 += v10 * as_v[nt][0] + v11 * as_v[nt][1];
                pd0 += v00 * ad_v[nt][0] + v01 * ad_v[nt][1];
                pd1 += v10 * ad_v[nt][0] + v11 * ad_v[nt][1];
            }
        }
        if (FUSE_ESED) {
            #pragma unroll
            for (int o = 1; o <= 2; o <<= 1) {
                pe0 += __shfl_xor_sync(0xffffffffu, pe0, o);
                pe1 += __shfl_xor_sync(0xffffffffu, pe1, o);
                pd0 += __shfl_xor_sync(0xffffffffu, pd0, o);
                pd1 += __shfl_xor_sync(0xffffffffu, pd1, o);
            }
            if (tig == 0) {
                int lr = wm * 32 + mt * 16 + gid;
                atomicAdd(&es_s[lr], pe0);     atomicAdd(&es_s[lr + 8], pe1);
                atomicAdd(&ed_s[lr], pd0);     atomicAdd(&ed_s[lr + 8], pd1);
            }
        }
    }

    if (FUSE_ESED) {
        __syncthreads();
        if (tid < 64 && brow + tid < M) {
            g_es[brow + tid] = es_s[tid];
            g_ed[brow + tid] = ed_s[tid];
        }
    }
}

// mlp1: g_h = x @ W1 + b1 (fp32 out)
__global__ void __launch_bounds__(256, 4) k_mma_x(const float* __restrict__ A,
                                                  const float* __restrict__ B,
                                                  const float* __restrict__ bias) {
    mma_gemm_body<false, false>(A, B, bias, nullptr, nullptr, g_h, NN);
}

// per-layer: g_hpf = fp16(h @ Wg[l]), fused es/ed
__global__ void __launch_bounds__(256, 4) k_mma_h(const float* __restrict__ B,
                                                  const float* __restrict__ asrc,
                                                  const float* __restrict__ adst) {
    mma_gemm_body<true, true>(g_h, B, nullptr, asrc, adst, nullptr, NN);
}

// ---------------------------------------------------------------------------
// GAT aggregation (warp per destination node, compact CSR) — single pass,
// no max-shift softmax, fp16 gather, x4 batched loads.
// ---------------------------------------------------------------------------
__global__ void k_gat_aggr(const float* __restrict__ bg) {
    int warp = (blockIdx.x * blockDim.x + threadIdx.x) >> 5;
    int lane = threadIdx.x & 31;
    if (warp >= NN) return;
    const int d = warp;
    const int lo = g_start[d], hi = lo + g_deg[d];
    const float ed_d = g_ed[d];
    const float e_self = leaky(g_es[d] + ed_d);

    float ex_self = expf(e_self);
    float z = ex_self;
    uint2 sv = *(const uint2*)&g_hpf[(size_t)d * 128 + 4 * lane];
    float2 s0 = __half22float2(*(half2*)&sv.x);
    float2 s1 = __half22float2(*(half2*)&sv.y);
    float ax = ex_self * s0.x, ay = ex_self * s0.y;
    float az = ex_self * s1.x, aw = ex_self * s1.y;

    const size_t fo = 4 * lane;
    int j = lo;

    for (; j + 4 <= hi; j += 4) {
        int i0 = g_csrc[j],     i1 = g_csrc[j + 1];
        int i2 = g_csrc[j + 2], i3 = g_csrc[j + 3];
        float e0 = g_es[i0], e1 = g_es[i1], e2 = g_es[i2], e3 = g_es[i3];
        uint2 w0 = *(const uint2*)&g_hpf[(size_t)i0 * 128 + fo];
        uint2 w1 = *(const uint2*)&g_hpf[(size_t)i1 * 128 + fo];
        uint2 w2 = *(const uint2*)&g_hpf[(size_t)i2 * 128 + fo];
        uint2 w3 = *(const uint2*)&g_hpf[(size_t)i3 * 128 + fo];

        float x0 = expf(leaky(e0 + ed_d));
        float x1 = expf(leaky(e1 + ed_d));
        float x2 = expf(leaky(e2 + ed_d));
        float x3 = expf(leaky(e3 + ed_d));
        z += (x0 + x1) + (x2 + x3);

        float2 a0 = __half22float2(*(half2*)&w0.x), b0 = __half22float2(*(half2*)&w0.y);
        float2 a1 = __half22float2(*(half2*)&w1.x), b1 = __half22float2(*(half2*)&w1.y);
        float2 a2 = __half22float2(*(half2*)&w2.x), b2 = __half22float2(*(half2*)&w2.y);
        float2 a3 = __half22float2(*(half2*)&w3.x), b3 = __half22float2(*(half2*)&w3.y);

        ax = fmaf(x0, a0.x, ax); ay = fmaf(x0, a0.y, ay);
        az = fmaf(x0, b0.x, az); aw = fmaf(x0, b0.y, aw);
        ax = fmaf(x1, a1.x, ax); ay = fmaf(x1, a1.y, ay);
        az = fmaf(x1, b1.x, az); aw = fmaf(x1, b1.y, aw);
        ax = fmaf(x2, a2.x, ax); ay = fmaf(x2, a2.y, ay);
        az = fmaf(x2, b2.x, az); aw = fmaf(x2, b2.y, aw);
        ax = fmaf(x3, a3.x, ax); ay = fmaf(x3, a3.y, ay);
        az = fmaf(x3, b3.x, az); aw = fmaf(x3, b3.y, aw);
    }

    for (; j < hi; ++j) {
        int s = g_csrc[j];
        float ex = expf(leaky(g_es[s] + ed_d));
        z += ex;
        uint2 wv = *(const uint2*)&g_hpf[(size_t)s * 128 + fo];
        float2 w0 = __half22float2(*(half2*)&wv.x);
        float2 w1 = __half22float2(*(half2*)&wv.y);
        ax = fmaf(ex, w0.x, ax);
        ay = fmaf(ex, w0.y, ay);
        az = fmaf(ex, w1.x, az);
        aw = fmaf(ex, w1.y, aw);
    }
    const float invz = 1.0f / z;

    float4* h4 = (float4*)g_h;
    float4 b = ((const float4*)bg)[lane];
    float4 hin = h4[(size_t)d * 32 + lane];
    float4 o;
    o.x = fmaxf(fmaf(ax, invz, b.x), 0.f) + hin.x;
    o.y = fmaxf(fmaf(ay, invz, b.y), 0.f) + hin.y;
    o.z = fmaxf(fmaf(az, invz, b.z), 0.f) + hin.z;
    o.w = fmaxf(fmaf(aw, invz, b.w), 0.f) + hin.w;
    h4[(size_t)d * 32 + lane] = o;
}

// ---------------------------------------------------------------------------
// Fused pool + final projection; re-zeroes g_deg/g_total for the next run.
// ---------------------------------------------------------------------------
__global__ void k_poolfinal(const void* __restrict__ ei,
                            const void* __restrict__ batch,
                            const float* __restrict__ W2,
                            const float* __restrict__ b2,
                            float* __restrict__ out) {
    __shared__ float ps[128];
    __shared__ int s_lo, s_hi, s64;
    const int g = blockIdx.x;
    const int tid = threadIdx.x;
    probe_is64(ei, &s64);
    __syncthreads();
    if (tid == 0) {
        int lo = 0, hi = NN;
        while (lo < hi) { int mid = (lo + hi) >> 1; if (load_idx2(batch, mid, s64) < g) lo = mid + 1; else hi = mid; }
        s_lo = lo;
        lo = 0; hi = NN;
        int g1 = g + 1;
        while (lo < hi) { int mid = (lo + hi) >> 1; if (load_idx2(batch, mid, s64) < g1) lo = mid + 1; else hi = mid; }
        s_hi = lo;
    }
    __syncthreads();
    float acc = 0.f;
    for (int i = s_lo; i < s_hi; ++i) acc += g_h[(size_t)i * 128 + tid];
    ps[tid] = acc;
    __syncthreads();
    if (tid < 64) {
        float o = b2[tid];
        #pragma unroll 8
        for (int k = 0; k < 128; ++k)
            o = fmaf(ps[k], W2[k * 64 + tid], o);
        out[g * 64 + tid] = o;
    }
    // reset CSR counters for the next invocation
    for (int i = g * 128 + tid; i < NN; i += NG * 128) g_deg[i] = 0;
    if (g == 0 && tid == 0) g_total = 0;
}

// ---------------------------------------------------------------------------
// Launch (11 kernels)
// ---------------------------------------------------------------------------
extern "C" void kernel_launch(void* const* d_in, const int* in_sizes, int n_in,
                              void* d_out, int out_size) {
    const float* x     = (const float*)d_in[0];
    const void*  ei    = d_in[1];
    const void*  batch = d_in[2];
    const float* W1    = (const float*)d_in[3];
    const float* b1    = (const float*)d_in[4];
    const float* Wg    = (const float*)d_in[5];
    const float* asrc  = (const float*)d_in[6];
    const float* adst  = (const float*)d_in[7];
    const float* bg    = (const float*)d_in[8];
    const float* W2    = (const float*)d_in[9];
    const float* b2    = (const float*)d_in[10];
    float*       out   = (float*)d_out;

    k_hist<<<(EE + 255) / 256, 256>>>(ei);
    k_alloc<<<(NN + 255) / 256, 256>>>();
    k_scatter<<<(EE + 255) / 256, 256>>>(ei);

    const int gemm_blocks = (NN + 63) / 64;
    const int node_warp_blocks = (NN * 32 + 255) / 256;

    k_mma_x<<<gemm_blocks, 256>>>(x, W1, b1);

    for (int l = 0; l < NLAYERS; ++l) {
        k_mma_h<<<gemm_blocks, 256>>>(Wg + (size_t)l * 128 * 128,
                                      asrc + l * 128, adst + l * 128);
        k_gat_aggr<<<node_warp_blocks, 256>>>(bg + l * 128);
    }

    k_poolfinal<<<NG, 128>>>(ei, batch, W2, b2, out);
}